// round 3
// baseline (speedup 1.0000x reference)
#include <cuda_runtime.h>
#include <math.h>

#define SQ 2048
#define NH 16
#define ID 128
#define ROPE 64
#define NOPE 128
#define VDIM 128
#define KVL 512
#define QD 576
#define HIDD 2048
#define QLORA 1536
#define TOPKK 1024
#define EPSV 1e-6f
#define SCALV 0.08838834764831845f  /* 128^-0.5 */

// ---------------- scratch (device globals; no runtime allocation) ----------------
__device__ float g_ckv[SQ * ID];
__device__ float g_ik[SQ * ID];
__device__ float g_ql[SQ * NH * ID];
__device__ float g_iq[SQ * NH * ID];
__device__ float g_wt[SQ * NH];
__device__ float g_w[SQ * NH];
__device__ float g_q[SQ * NH * QD];
__device__ float g_kv[SQ * QD];
__device__ float g_score[SQ * SQ];
__device__ unsigned char g_mask[SQ * SQ];
__device__ float g_P[(size_t)NH * SQ * SQ];
__device__ float g_ao[(size_t)NH * SQ * KVL];

// ---------------- generic tiled SGEMM: C = A @ B(^T) ----------------
// A: M x K row-major (lda). TRANSB: B is N x K row-major (ldb=K-stride); else B is K x N (ldb=N-stride).
// CAUSAL_N: skip output tiles fully above the diagonal (N dim indexes keys).
// CAUSAL_K: limit K loop to k <= row_max (K dim indexes keys).
template <int TRANSB, int CAUSAL_N, int CAUSAL_K>
__global__ void sgemm_k(const float* __restrict__ Ag, const float* __restrict__ Bg,
                        float* __restrict__ Cg, int M, int N, int K,
                        int lda, int ldb, int ldc,
                        long aB, long bB, long cB) {
    constexpr int BM = 64, BN = 64, BK = 16;
    int bm = blockIdx.y, bn = blockIdx.x;
    if (CAUSAL_N && bn * BN > bm * BM + BM - 1) return;
    const float* A = Ag + (long)blockIdx.z * aB;
    const float* B = Bg + (long)blockIdx.z * bB;
    float* C = Cg + (long)blockIdx.z * cB;
    __shared__ float As[BK][BM];
    __shared__ float Bs[BK][BN];
    int tid = threadIdx.x;
    int tx = tid & 15, ty = tid >> 4;
    float acc[4][4];
#pragma unroll
    for (int i = 0; i < 4; i++)
#pragma unroll
        for (int j = 0; j < 4; j++) acc[i][j] = 0.f;
    int kEnd = K;
    if (CAUSAL_K) kEnd = min(K, bm * BM + BM);
    int arow = tid >> 2, akq = (tid & 3) << 2;
    for (int k0 = 0; k0 < kEnd; k0 += BK) {
        float4 av = *(const float4*)(A + (long)(bm * BM + arow) * lda + (k0 + akq));
        As[akq + 0][arow] = av.x; As[akq + 1][arow] = av.y;
        As[akq + 2][arow] = av.z; As[akq + 3][arow] = av.w;
        if (TRANSB) {
            int bl = tid >> 2;
            int brow = bn * BN + bl;
            int kq = (tid & 3) << 2;
            float4 bv = make_float4(0.f, 0.f, 0.f, 0.f);
            if (brow < N) bv = *(const float4*)(B + (long)brow * ldb + (k0 + kq));
            Bs[kq + 0][bl] = bv.x; Bs[kq + 1][bl] = bv.y;
            Bs[kq + 2][bl] = bv.z; Bs[kq + 3][bl] = bv.w;
        } else {
            int bk = tid >> 4;
            int bc = (tid & 15) << 2;
            int bcol = bn * BN + bc;
            float4 bv = make_float4(0.f, 0.f, 0.f, 0.f);
            if (bcol < N) bv = *(const float4*)(B + (long)(k0 + bk) * ldb + bcol);
            Bs[bk][bc + 0] = bv.x; Bs[bk][bc + 1] = bv.y;
            Bs[bk][bc + 2] = bv.z; Bs[bk][bc + 3] = bv.w;
        }
        __syncthreads();
#pragma unroll
        for (int kk = 0; kk < BK; kk++) {
            float4 a4 = *(const float4*)&As[kk][ty << 2];
            float4 b4 = *(const float4*)&Bs[kk][tx << 2];
            float a[4] = {a4.x, a4.y, a4.z, a4.w};
            float b[4] = {b4.x, b4.y, b4.z, b4.w};
#pragma unroll
            for (int i = 0; i < 4; i++)
#pragma unroll
                for (int j = 0; j < 4; j++) acc[i][j] += a[i] * b[j];
        }
        __syncthreads();
    }
#pragma unroll
    for (int i = 0; i < 4; i++) {
        int row = bm * BM + (ty << 2) + i;
#pragma unroll
        for (int j = 0; j < 4; j++) {
            int col = bn * BN + (tx << 2) + j;
            if (col < N) C[(long)row * ldc + col] = acc[i][j];
        }
    }
}

// ---------------- index_k: rope(interleaved, deinterleaved output) + rmsnorm ----------------
__global__ void indexk_kernel(const float* __restrict__ ckv, const float* __restrict__ cosb,
                              const float* __restrict__ sinb, const float* __restrict__ knorm,
                              float* __restrict__ ik) {
    int s = blockIdx.x, j = threadIdx.x;  // 128 threads
    __shared__ float sh[128];
    __shared__ float red[128];
    sh[j] = ckv[s * 128 + j];
    __syncthreads();
    float x = (j >= 64) ? sh[j] * sh[j] : 0.f;
    red[j] = x;
    __syncthreads();
    for (int t = 64; t > 0; t >>= 1) {
        if (j < t) red[j] += red[j + t];
        __syncthreads();
    }
    float rstd = rsqrtf(red[0] / 64.f + EPSV);
    float o;
    if (j < 64) {
        float c = cosb[s * 64 + j], si = sinb[s * 64 + j];  // cos/sin halves duplicated
        int jj = j & 31;
        float e = sh[2 * jj], od = sh[2 * jj + 1];
        o = (j < 32) ? (e * c - od * si) : (od * c + e * si);
    } else {
        o = sh[j] * rstd * knorm[j - 64];
    }
    ik[s * 128 + j] = o;
}

// ---------------- index_q: rope first 64 of each 128-chunk ----------------
__global__ void indexq_kernel(const float* __restrict__ ql, const float* __restrict__ cosb,
                              const float* __restrict__ sinb, float* __restrict__ iq) {
    int s = blockIdx.x;
    int tid = threadIdx.x;  // 256
    __shared__ float sh[2048];
    for (int i = tid; i < 2048; i += 256) sh[i] = ql[(long)s * 2048 + i];
    __syncthreads();
    for (int i = tid; i < 2048; i += 256) {
        int h = i >> 7, j = i & 127;
        float o;
        if (j < 64) {
            int jj = j & 31;
            float c = cosb[s * 64 + j], si = sinb[s * 64 + j];
            float e = sh[h * 128 + 2 * jj], od = sh[h * 128 + 2 * jj + 1];
            o = (j < 32) ? (e * c - od * si) : (od * c + e * si);
        } else {
            o = sh[h * 128 + j];
        }
        iq[(long)s * 2048 + i] = o;
    }
}

__global__ void absbias_kernel(const float* __restrict__ wt, const float* __restrict__ b,
                               float* __restrict__ w) {
    int i = blockIdx.x * 256 + threadIdx.x;
    if (i < SQ * NH) w[i] = fabsf(wt[i] + b[i & 15]);
}

__global__ void qrot_kernel(const float* __restrict__ qr, float* __restrict__ q) {
    int i = blockIdx.x * 256 + threadIdx.x;
    if (i >= NH * SQ * ROPE) return;
    int h = i / (SQ * ROPE);
    int r = i % (SQ * ROPE);
    int s = r / ROPE, j = r % ROPE;
    q[((long)s * NH + h) * QD + KVL + j] = qr[i];
}

__global__ void kvbuild_kernel(const float* __restrict__ kp, const float* __restrict__ kr,
                               float* __restrict__ kv) {
    int i = blockIdx.x * 256 + threadIdx.x;
    if (i >= SQ * QD) return;
    int s = i / QD, j = i % QD;
    kv[i] = (j < KVL) ? kp[s * KVL + j] : kr[s * ROPE + (j - KVL)];
}

// ---------------- indexer score: score[q,k] = SCAL * sum_h w[q,h]*relu(iq[q,h]·ik[k]) ----------------
__global__ void idx_score_kernel(const float* __restrict__ iq, const float* __restrict__ ik,
                                 const float* __restrict__ w, float* __restrict__ score) {
    int bq = blockIdx.y, bk = blockIdx.x;
    if (bk * 32 > bq * 32 + 31) return;  // strictly-above-diagonal tiles never read
    __shared__ float iqs[32][132];
    __shared__ float iks[32][132];
    __shared__ float ws[32][16];
    int tid = threadIdx.x;  // 256
    for (int idx = tid; idx < 32 * 128; idx += 256) {
        int r = idx >> 7, c = idx & 127;
        iks[r][c] = ik[(bk * 32 + r) * 128 + c];
    }
    for (int idx = tid; idx < 32 * 16; idx += 256) {
        int r = idx >> 4, c = idx & 15;
        ws[r][c] = w[(bq * 32 + r) * 16 + c];
    }
    int tx = tid & 15, ty = tid >> 4;
    int q0 = ty * 2, q1 = q0 + 1, k0 = tx * 2, k1 = k0 + 1;
    float s00 = 0, s01 = 0, s10 = 0, s11 = 0;
    for (int h = 0; h < 16; h++) {
        __syncthreads();
        for (int idx = tid; idx < 32 * 128; idx += 256) {
            int r = idx >> 7, c = idx & 127;
            iqs[r][c] = iq[((long)(bq * 32 + r) * 16 + h) * 128 + c];
        }
        __syncthreads();
        float d00 = 0, d01 = 0, d10 = 0, d11 = 0;
#pragma unroll 4
        for (int d = 0; d < 128; d++) {
            float a0 = iqs[q0][d], a1 = iqs[q1][d];
            float b0 = iks[k0][d], b1 = iks[k1][d];
            d00 += a0 * b0; d01 += a0 * b1;
            d10 += a1 * b0; d11 += a1 * b1;
        }
        float w0 = ws[q0][h], w1 = ws[q1][h];
        s00 += w0 * fmaxf(d00, 0.f); s01 += w0 * fmaxf(d01, 0.f);
        s10 += w1 * fmaxf(d10, 0.f); s11 += w1 * fmaxf(d11, 0.f);
    }
    long rq0 = (long)(bq * 32 + q0) * SQ, rq1 = (long)(bq * 32 + q1) * SQ;
    score[rq0 + bk * 32 + k0] = s00 * SCALV;
    score[rq0 + bk * 32 + k1] = s01 * SCALV;
    score[rq1 + bk * 32 + k0] = s10 * SCALV;
    score[rq1 + bk * 32 + k1] = s11 * SCALV;
}

// ---------------- per-query top-1024 via radix select (scores are all >= 0) ----------------
__global__ void topk_kernel(const float* __restrict__ score, unsigned char* __restrict__ mask) {
    int q = blockIdx.x;
    int n = q + 1;
    int tid = threadIdx.x;  // 256
    unsigned char* mrow = mask + (long)q * SQ;
    if (q < TOPKK) {  // all causal keys selected
        for (int k = tid; k < SQ; k += 256) mrow[k] = (k <= q) ? 1 : 0;
        return;
    }
    const float* srow = score + (long)q * SQ;
    __shared__ unsigned int sbits[SQ];
    __shared__ int hist[256];
    __shared__ unsigned int sh_prefix;
    __shared__ int sh_kk;
    for (int k = tid; k < n; k += 256) sbits[k] = __float_as_uint(srow[k]);
    if (tid == 0) { sh_prefix = 0u; sh_kk = TOPKK; }
    __syncthreads();
    for (int pass = 0; pass < 4; pass++) {
        int shift = 24 - 8 * pass;
        if (tid < 256) hist[tid] = 0;
        __syncthreads();
        unsigned int pfx = sh_prefix;
        for (int k = tid; k < n; k += 256) {
            unsigned int v = sbits[k];
            if ((unsigned int)(((unsigned long long)v) >> (shift + 8)) == pfx)
                atomicAdd(&hist[(v >> shift) & 255], 1);
        }
        __syncthreads();
        if (tid == 0) {
            int kk = sh_kk;
            int d = 255;
            for (; d >= 0; d--) {
                if (kk <= hist[d]) break;
                kk -= hist[d];
            }
            sh_prefix = (pfx << 8) | (unsigned int)d;
            sh_kk = kk;
        }
        __syncthreads();
    }
    unsigned int T = sh_prefix;
    int kk = sh_kk;  // number of ties (== T) to keep, lowest index first (matches lax.top_k)
    for (int k = tid; k < SQ; k += 256) {
        unsigned char m = 0;
        if (k < n) {
            unsigned int v = sbits[k];
            if (v > T) m = 1;
            else if (v == T) {
                int rank = 0;
                for (int j = 0; j < k; j++) rank += (sbits[j] == T) ? 1 : 0;
                m = (rank < kk) ? 1 : 0;
            }
        }
        mrow[k] = m;
    }
}

// ---------------- masked softmax over keys (writes probabilities, 0 where masked) ----------------
__global__ void softmax_kernel(float* __restrict__ P, const unsigned char* __restrict__ mask) {
    int q = blockIdx.x, h = blockIdx.y;
    float* row = P + ((long)h * SQ + q) * SQ;
    const unsigned char* mrow = mask + (long)q * SQ;
    int tid = threadIdx.x;  // 256
    float v[8];
    unsigned char m[8];
    float mx = -1e30f;
#pragma unroll
    for (int i = 0; i < 8; i++) {
        int k = i * 256 + tid;
        m[i] = mrow[k];
        float val = m[i] ? row[k] * SCALV : -1e30f;
        v[i] = val;
        mx = fmaxf(mx, val);
    }
    __shared__ float red[256];
    red[tid] = mx;
    __syncthreads();
    for (int t = 128; t > 0; t >>= 1) {
        if (tid < t) red[tid] = fmaxf(red[tid], red[tid + t]);
        __syncthreads();
    }
    mx = red[0];
    __syncthreads();
    float sum = 0.f;
#pragma unroll
    for (int i = 0; i < 8; i++) {
        if (m[i]) { v[i] = __expf(v[i] - mx); sum += v[i]; }
        else v[i] = 0.f;
    }
    red[tid] = sum;
    __syncthreads();
    for (int t = 128; t > 0; t >>= 1) {
        if (tid < t) red[tid] += red[tid + t];
        __syncthreads();
    }
    float inv = 1.f / red[0];
#pragma unroll
    for (int i = 0; i < 8; i++) row[i * 256 + tid] = v[i] * inv;
}

// ---------------- launch ----------------
extern "C" void kernel_launch(void* const* d_in, const int* in_sizes, int n_in,
                              void* d_out, int out_size) {
    const float* q_latent = (const float*)d_in[0];
    const float* hidden   = (const float*)d_in[1];
    const float* cosb     = (const float*)d_in[2];
    const float* sinb     = (const float*)d_in[3];
    const float* q_pass   = (const float*)d_in[4];
    const float* q_rot    = (const float*)d_in[5];
    const float* k_pass   = (const float*)d_in[6];
    const float* k_rot    = (const float*)d_in[7];
    /* d_in[8] = position_ids (unused by reference) */
    const float* kv_b     = (const float*)d_in[9];
    const float* wq_b     = (const float*)d_in[10];
    const float* wk       = (const float*)d_in[11];
    const float* knorm    = (const float*)d_in[12];
    const float* wproj    = (const float*)d_in[13];
    const float* wproj_b  = (const float*)d_in[14];
    float* out = (float*)d_out;

    float *ckv, *ik, *ql, *iq, *wt, *w, *q, *kv, *score, *P, *ao;
    unsigned char* mask;
    cudaGetSymbolAddress((void**)&ckv, g_ckv);
    cudaGetSymbolAddress((void**)&ik, g_ik);
    cudaGetSymbolAddress((void**)&ql, g_ql);
    cudaGetSymbolAddress((void**)&iq, g_iq);
    cudaGetSymbolAddress((void**)&wt, g_wt);
    cudaGetSymbolAddress((void**)&w, g_w);
    cudaGetSymbolAddress((void**)&q, g_q);
    cudaGetSymbolAddress((void**)&kv, g_kv);
    cudaGetSymbolAddress((void**)&score, g_score);
    cudaGetSymbolAddress((void**)&mask, g_mask);
    cudaGetSymbolAddress((void**)&P, g_P);
    cudaGetSymbolAddress((void**)&ao, g_ao);

    // 1. ckv = hidden @ wk^T   (2048x128)
    sgemm_k<1, 0, 0><<<dim3(2, 32, 1), 256>>>(hidden, wk, ckv, SQ, ID, HIDD,
                                              HIDD, HIDD, ID, 0, 0, 0);
    // 2. index_k (rope + rmsnorm)
    indexk_kernel<<<SQ, 128>>>(ckv, cosb, sinb, knorm, ik);
    // 3. ql = q_latent @ wq_b^T   (2048x2048)
    sgemm_k<1, 0, 0><<<dim3(32, 32, 1), 256>>>(q_latent, wq_b, ql, SQ, NH * ID, QLORA,
                                               QLORA, QLORA, NH * ID, 0, 0, 0);
    // 4. index_q (rope on first 64 per head)
    indexq_kernel<<<SQ, 256>>>(ql, cosb, sinb, iq);
    // 5. w = |hidden @ wproj^T + b|
    sgemm_k<1, 0, 0><<<dim3(1, 32, 1), 256>>>(hidden, wproj, wt, SQ, NH, HIDD,
                                              HIDD, HIDD, NH, 0, 0, 0);
    absbias_kernel<<<(SQ * NH + 255) / 256, 256>>>(wt, wproj_b, w);
    // 6. q_abs[h] = q_pass[h] @ k_b[h]   (batched NN, z=16) -> q[:, :, 0:512]
    sgemm_k<0, 0, 0><<<dim3(8, 32, 16), 256>>>(q_pass, kv_b, q, SQ, KVL, NOPE,
                                               NOPE, KVL, NH * QD,
                                               (long)SQ * NOPE, (long)256 * KVL, (long)QD);
    qrot_kernel<<<(NH * SQ * ROPE + 255) / 256, 256>>>(q_rot, q);
    kvbuild_kernel<<<(SQ * QD + 255) / 256, 256>>>(k_pass, k_rot, kv);
    // 7. indexer scores (causal tiles only)
    idx_score_kernel<<<dim3(64, 64), 256>>>(iq, ik, w, score);
    // 8. top-1024 mask per query
    topk_kernel<<<SQ, 256>>>(score, mask);
    // 9. logits[h] = q[:,h,:] @ kv^T   (batched NT, causal-N skip)
    sgemm_k<1, 1, 0><<<dim3(32, 32, 16), 256>>>(q, kv, P, SQ, SQ, QD,
                                                NH * QD, QD, SQ,
                                                (long)QD, 0L, (long)SQ * SQ);
    // 10. masked softmax
    softmax_kernel<<<dim3(SQ, NH), 256>>>(P, mask);
    // 11. attn_out[h] = P[h] @ kv[:, :512]   (batched NN, causal-K limit)
    sgemm_k<0, 0, 1><<<dim3(8, 32, 16), 256>>>(P, kv, ao, SQ, KVL, SQ,
                                               SQ, QD, KVL,
                                               (long)SQ * SQ, 0L, (long)SQ * KVL);
    // 12. out[s,h,:] = attn_out[h,s,:] @ v_b[h]^T   (batched NT)
    sgemm_k<1, 0, 0><<<dim3(2, 32, 16), 256>>>(ao, kv_b + NOPE * KVL, out, SQ, VDIM, KVL,
                                               KVL, KVL, NH * VDIM,
                                               (long)SQ * KVL, (long)256 * KVL, (long)VDIM);
}

// round 6
// speedup vs baseline: 1.5862x; 1.5862x over previous
#include <cuda_runtime.h>
#include <math.h>

#define SQ 2048
#define NH 16
#define ID 128
#define ROPE 64
#define NOPE 128
#define VDIM 128
#define KVL 512
#define KC 192          /* compressed logit K-dim: NOPE + ROPE */
#define HIDD 2048
#define QLORA 1536
#define TOPKK 1024
#define EPSV 1e-6f
#define SCALV 0.08838834764831845f  /* 128^-0.5 */

// ---------------- scratch (device globals; no runtime allocation) ----------------
__device__ float g_ckv[SQ * ID];
__device__ float g_ik[SQ * ID];
__device__ float g_ql[SQ * NH * ID];
__device__ float g_iq[SQ * NH * ID];
__device__ float g_wt[SQ * NH];
__device__ float g_w[SQ * NH];
__device__ float g_qcat[(size_t)NH * SQ * KC];   // [q_pass, q_rot] per head
__device__ float g_kcat[(size_t)NH * SQ * KC];   // [k_eff,  k_rot] per head
__device__ float g_ve[(size_t)NH * SQ * VDIM];   // v_eff per head
__device__ float g_score[SQ * SQ];
__device__ unsigned char g_mask[SQ * SQ];
__device__ float g_P[(size_t)NH * SQ * SQ];

// ---------------- generic tiled SGEMM: C = A @ B(^T) ----------------
template <int TRANSB, int CAUSAL_N, int CAUSAL_K>
__global__ void sgemm_k(const float* __restrict__ Ag, const float* __restrict__ Bg,
                        float* __restrict__ Cg, int M, int N, int K,
                        int lda, int ldb, int ldc,
                        long aB, long bB, long cB) {
    constexpr int BM = 64, BN = 64, BK = 16;
    int bm = blockIdx.y, bn = blockIdx.x;
    if (CAUSAL_N && bn * BN > bm * BM + BM - 1) return;
    const float* A = Ag + (long)blockIdx.z * aB;
    const float* B = Bg + (long)blockIdx.z * bB;
    float* C = Cg + (long)blockIdx.z * cB;
    __shared__ float As[BK][BM];
    __shared__ float Bs[BK][BN];
    int tid = threadIdx.x;
    int tx = tid & 15, ty = tid >> 4;
    float acc[4][4];
#pragma unroll
    for (int i = 0; i < 4; i++)
#pragma unroll
        for (int j = 0; j < 4; j++) acc[i][j] = 0.f;
    int kEnd = K;
    if (CAUSAL_K) kEnd = min(K, bm * BM + BM);
    int arow = tid >> 2, akq = (tid & 3) << 2;
    for (int k0 = 0; k0 < kEnd; k0 += BK) {
        float4 av = *(const float4*)(A + (long)(bm * BM + arow) * lda + (k0 + akq));
        As[akq + 0][arow] = av.x; As[akq + 1][arow] = av.y;
        As[akq + 2][arow] = av.z; As[akq + 3][arow] = av.w;
        if (TRANSB) {
            int bl = tid >> 2;
            int brow = bn * BN + bl;
            int kq = (tid & 3) << 2;
            float4 bv = make_float4(0.f, 0.f, 0.f, 0.f);
            if (brow < N) bv = *(const float4*)(B + (long)brow * ldb + (k0 + kq));
            Bs[kq + 0][bl] = bv.x; Bs[kq + 1][bl] = bv.y;
            Bs[kq + 2][bl] = bv.z; Bs[kq + 3][bl] = bv.w;
        } else {
            int bk = tid >> 4;
            int bc = (tid & 15) << 2;
            int bcol = bn * BN + bc;
            float4 bv = make_float4(0.f, 0.f, 0.f, 0.f);
            if (bcol < N) bv = *(const float4*)(B + (long)(k0 + bk) * ldb + bcol);
            Bs[bk][bc + 0] = bv.x; Bs[bk][bc + 1] = bv.y;
            Bs[bk][bc + 2] = bv.z; Bs[bk][bc + 3] = bv.w;
        }
        __syncthreads();
#pragma unroll
        for (int kk = 0; kk < BK; kk++) {
            float4 a4 = *(const float4*)&As[kk][ty << 2];
            float4 b4 = *(const float4*)&Bs[kk][tx << 2];
            float a[4] = {a4.x, a4.y, a4.z, a4.w};
            float b[4] = {b4.x, b4.y, b4.z, b4.w};
#pragma unroll
            for (int i = 0; i < 4; i++)
#pragma unroll
                for (int j = 0; j < 4; j++) acc[i][j] += a[i] * b[j];
        }
        __syncthreads();
    }
#pragma unroll
    for (int i = 0; i < 4; i++) {
        int row = bm * BM + (ty << 2) + i;
#pragma unroll
        for (int j = 0; j < 4; j++) {
            int col = bn * BN + (tx << 2) + j;
            if (col < N) C[(long)row * ldc + col] = acc[i][j];
        }
    }
}

// ---------------- index_k: rope(interleaved) + rmsnorm ----------------
__global__ void indexk_kernel(const float* __restrict__ ckv, const float* __restrict__ cosb,
                              const float* __restrict__ sinb, const float* __restrict__ knorm,
                              float* __restrict__ ik) {
    int s = blockIdx.x, j = threadIdx.x;  // 128 threads
    __shared__ float sh[128];
    __shared__ float red[128];
    sh[j] = ckv[s * 128 + j];
    __syncthreads();
    float x = (j >= 64) ? sh[j] * sh[j] : 0.f;
    red[j] = x;
    __syncthreads();
    for (int t = 64; t > 0; t >>= 1) {
        if (j < t) red[j] += red[j + t];
        __syncthreads();
    }
    float rstd = rsqrtf(red[0] / 64.f + EPSV);
    float o;
    if (j < 64) {
        float c = cosb[s * 64 + j], si = sinb[s * 64 + j];
        int jj = j & 31;
        float e = sh[2 * jj], od = sh[2 * jj + 1];
        o = (j < 32) ? (e * c - od * si) : (od * c + e * si);
    } else {
        o = sh[j] * rstd * knorm[j - 64];
    }
    ik[s * 128 + j] = o;
}

// ---------------- index_q: rope first 64 of each 128-chunk ----------------
__global__ void indexq_kernel(const float* __restrict__ ql, const float* __restrict__ cosb,
                              const float* __restrict__ sinb, float* __restrict__ iq) {
    int s = blockIdx.x;
    int tid = threadIdx.x;  // 256
    __shared__ float sh[2048];
    for (int i = tid; i < 2048; i += 256) sh[i] = ql[(long)s * 2048 + i];
    __syncthreads();
    for (int i = tid; i < 2048; i += 256) {
        int h = i >> 7, j = i & 127;
        float o;
        if (j < 64) {
            int jj = j & 31;
            float c = cosb[s * 64 + j], si = sinb[s * 64 + j];
            float e = sh[h * 128 + 2 * jj], od = sh[h * 128 + 2 * jj + 1];
            o = (j < 32) ? (e * c - od * si) : (od * c + e * si);
        } else {
            o = sh[h * 128 + j];
        }
        iq[(long)s * 2048 + i] = o;
    }
}

__global__ void absbias_kernel(const float* __restrict__ wt, const float* __restrict__ b,
                               float* __restrict__ w) {
    int i = blockIdx.x * 256 + threadIdx.x;
    if (i < SQ * NH) w[i] = fabsf(wt[i] + b[i & 15]);
}

// qcat[h][s][0:128] = q_pass[h][s], qcat[h][s][128:192] = q_rot[h][s]
__global__ void qcat_kernel(const float* __restrict__ qp, const float* __restrict__ qr,
                            float* __restrict__ qc) {
    long i = (long)blockIdx.x * 256 + threadIdx.x;
    if (i >= (long)NH * SQ * KC) return;
    int d = (int)(i % KC);
    long r = i / KC;
    int s = (int)(r % SQ);
    int h = (int)(r / SQ);
    qc[i] = (d < NOPE) ? qp[((long)h * SQ + s) * NOPE + d]
                       : qr[((long)h * SQ + s) * ROPE + (d - NOPE)];
}

// kcat[h][k][128:192] = k_rot[k]   (cols 0:128 filled by the k_eff GEMM)
__global__ void krot_kernel(const float* __restrict__ kr, float* __restrict__ kc) {
    long i = (long)blockIdx.x * 256 + threadIdx.x;
    if (i >= (long)NH * SQ * ROPE) return;
    int j = (int)(i % ROPE);
    long r = i / ROPE;
    int s = (int)(r % SQ);
    int h = (int)(r / SQ);
    kc[((long)h * SQ + s) * KC + NOPE + j] = kr[s * ROPE + j];
}

// ---------------- indexer score ----------------
__global__ void idx_score_kernel(const float* __restrict__ iq, const float* __restrict__ ik,
                                 const float* __restrict__ w, float* __restrict__ score) {
    int bq = blockIdx.y, bk = blockIdx.x;
    if (bk * 32 > bq * 32 + 31) return;
    __shared__ float iqs[32][132];
    __shared__ float iks[32][132];
    __shared__ float ws[32][16];
    int tid = threadIdx.x;  // 256
    for (int idx = tid; idx < 32 * 128; idx += 256) {
        int r = idx >> 7, c = idx & 127;
        iks[r][c] = ik[(bk * 32 + r) * 128 + c];
    }
    for (int idx = tid; idx < 32 * 16; idx += 256) {
        int r = idx >> 4, c = idx & 15;
        ws[r][c] = w[(bq * 32 + r) * 16 + c];
    }
    int tx = tid & 15, ty = tid >> 4;
    int q0 = ty * 2, q1 = q0 + 1, k0 = tx * 2, k1 = k0 + 1;
    float s00 = 0, s01 = 0, s10 = 0, s11 = 0;
    for (int h = 0; h < 16; h++) {
        __syncthreads();
        for (int idx = tid; idx < 32 * 128; idx += 256) {
            int r = idx >> 7, c = idx & 127;
            iqs[r][c] = iq[((long)(bq * 32 + r) * 16 + h) * 128 + c];
        }
        __syncthreads();
        float d00 = 0, d01 = 0, d10 = 0, d11 = 0;
#pragma unroll 4
        for (int d = 0; d < 128; d++) {
            float a0 = iqs[q0][d], a1 = iqs[q1][d];
            float b0 = iks[k0][d], b1 = iks[k1][d];
            d00 += a0 * b0; d01 += a0 * b1;
            d10 += a1 * b0; d11 += a1 * b1;
        }
        float w0 = ws[q0][h], w1 = ws[q1][h];
        s00 += w0 * fmaxf(d00, 0.f); s01 += w0 * fmaxf(d01, 0.f);
        s10 += w1 * fmaxf(d10, 0.f); s11 += w1 * fmaxf(d11, 0.f);
    }
    long rq0 = (long)(bq * 32 + q0) * SQ, rq1 = (long)(bq * 32 + q1) * SQ;
    score[rq0 + bk * 32 + k0] = s00 * SCALV;
    score[rq0 + bk * 32 + k1] = s01 * SCALV;
    score[rq1 + bk * 32 + k0] = s10 * SCALV;
    score[rq1 + bk * 32 + k1] = s11 * SCALV;
}

// ---------------- per-query top-1024 via radix select ----------------
__global__ void topk_kernel(const float* __restrict__ score, unsigned char* __restrict__ mask) {
    int q = blockIdx.x;
    int n = q + 1;
    int tid = threadIdx.x;  // 256
    unsigned char* mrow = mask + (long)q * SQ;
    if (q < TOPKK) {
        for (int k = tid; k < SQ; k += 256) mrow[k] = (k <= q) ? 1 : 0;
        return;
    }
    const float* srow = score + (long)q * SQ;
    __shared__ unsigned int sbits[SQ];
    __shared__ int hist[256];
    __shared__ unsigned int sh_prefix;
    __shared__ int sh_kk;
    for (int k = tid; k < n; k += 256) sbits[k] = __float_as_uint(srow[k]);
    if (tid == 0) { sh_prefix = 0u; sh_kk = TOPKK; }
    __syncthreads();
    for (int pass = 0; pass < 4; pass++) {
        int shift = 24 - 8 * pass;
        if (tid < 256) hist[tid] = 0;
        __syncthreads();
        unsigned int pfx = sh_prefix;
        for (int k = tid; k < n; k += 256) {
            unsigned int v = sbits[k];
            if ((unsigned int)(((unsigned long long)v) >> (shift + 8)) == pfx)
                atomicAdd(&hist[(v >> shift) & 255], 1);
        }
        __syncthreads();
        if (tid == 0) {
            int kk = sh_kk;
            int d = 255;
            for (; d >= 0; d--) {
                if (kk <= hist[d]) break;
                kk -= hist[d];
            }
            sh_prefix = (pfx << 8) | (unsigned int)d;
            sh_kk = kk;
        }
        __syncthreads();
    }
    unsigned int T = sh_prefix;
    int kk = sh_kk;
    for (int k = tid; k < SQ; k += 256) {
        unsigned char m = 0;
        if (k < n) {
            unsigned int v = sbits[k];
            if (v > T) m = 1;
            else if (v == T) {
                int rank = 0;
                for (int j = 0; j < k; j++) rank += (sbits[j] == T) ? 1 : 0;
                m = (rank < kk) ? 1 : 0;
            }
        }
        mrow[k] = m;
    }
}

// ---------------- masked softmax ----------------
__global__ void softmax_kernel(float* __restrict__ P, const unsigned char* __restrict__ mask) {
    int q = blockIdx.x, h = blockIdx.y;
    float* row = P + ((long)h * SQ + q) * SQ;
    const unsigned char* mrow = mask + (long)q * SQ;
    int tid = threadIdx.x;  // 256
    float v[8];
    unsigned char m[8];
    float mx = -1e30f;
#pragma unroll
    for (int i = 0; i < 8; i++) {
        int k = i * 256 + tid;
        m[i] = mrow[k];
        float val = m[i] ? row[k] * SCALV : -1e30f;
        v[i] = val;
        mx = fmaxf(mx, val);
    }
    __shared__ float red[256];
    red[tid] = mx;
    __syncthreads();
    for (int t = 128; t > 0; t >>= 1) {
        if (tid < t) red[tid] = fmaxf(red[tid], red[tid + t]);
        __syncthreads();
    }
    mx = red[0];
    __syncthreads();
    float sum = 0.f;
#pragma unroll
    for (int i = 0; i < 8; i++) {
        if (m[i]) { v[i] = __expf(v[i] - mx); sum += v[i]; }
        else v[i] = 0.f;
    }
    red[tid] = sum;
    __syncthreads();
    for (int t = 128; t > 0; t >>= 1) {
        if (tid < t) red[tid] += red[tid + t];
        __syncthreads();
    }
    float inv = 1.f / red[0];
#pragma unroll
    for (int i = 0; i < 8; i++) row[i * 256 + tid] = v[i] * inv;
}

// ---------------- launch ----------------
extern "C" void kernel_launch(void* const* d_in, const int* in_sizes, int n_in,
                              void* d_out, int out_size) {
    const float* q_latent = (const float*)d_in[0];
    const float* hidden   = (const float*)d_in[1];
    const float* cosb     = (const float*)d_in[2];
    const float* sinb     = (const float*)d_in[3];
    const float* q_pass   = (const float*)d_in[4];
    const float* q_rot    = (const float*)d_in[5];
    const float* k_pass   = (const float*)d_in[6];
    const float* k_rot    = (const float*)d_in[7];
    /* d_in[8] = position_ids (unused) */
    const float* kv_b     = (const float*)d_in[9];
    const float* wq_b     = (const float*)d_in[10];
    const float* wk       = (const float*)d_in[11];
    const float* knorm    = (const float*)d_in[12];
    const float* wproj    = (const float*)d_in[13];
    const float* wproj_b  = (const float*)d_in[14];
    float* out = (float*)d_out;

    float *ckv, *ik, *ql, *iq, *wt, *w, *qcat, *kcat, *ve, *score, *P;
    unsigned char* mask;
    cudaGetSymbolAddress((void**)&ckv, g_ckv);
    cudaGetSymbolAddress((void**)&ik, g_ik);
    cudaGetSymbolAddress((void**)&ql, g_ql);
    cudaGetSymbolAddress((void**)&iq, g_iq);
    cudaGetSymbolAddress((void**)&wt, g_wt);
    cudaGetSymbolAddress((void**)&w, g_w);
    cudaGetSymbolAddress((void**)&qcat, g_qcat);
    cudaGetSymbolAddress((void**)&kcat, g_kcat);
    cudaGetSymbolAddress((void**)&ve, g_ve);
    cudaGetSymbolAddress((void**)&score, g_score);
    cudaGetSymbolAddress((void**)&mask, g_mask);
    cudaGetSymbolAddress((void**)&P, g_P);

    // 1. ckv = hidden @ wk^T   (2048x128)
    sgemm_k<1, 0, 0><<<dim3(2, 32, 1), 256>>>(hidden, wk, ckv, SQ, ID, HIDD,
                                              HIDD, HIDD, ID, 0, 0, 0);
    // 2. index_k
    indexk_kernel<<<SQ, 128>>>(ckv, cosb, sinb, knorm, ik);
    // 3. ql = q_latent @ wq_b^T   (2048x2048)
    sgemm_k<1, 0, 0><<<dim3(32, 32, 1), 256>>>(q_latent, wq_b, ql, SQ, NH * ID, QLORA,
                                               QLORA, QLORA, NH * ID, 0, 0, 0);
    // 4. index_q
    indexq_kernel<<<SQ, 256>>>(ql, cosb, sinb, iq);
    // 5. w = |hidden @ wproj^T + b|
    sgemm_k<1, 0, 0><<<dim3(1, 32, 1), 256>>>(hidden, wproj, wt, SQ, NH, HIDD,
                                              HIDD, HIDD, NH, 0, 0, 0);
    absbias_kernel<<<(SQ * NH + 255) / 256, 256>>>(wt, wproj_b, w);
    // 6. k_eff[h] = k_pass @ k_b[h]^T  -> kcat cols 0:128  (batched z=16)
    sgemm_k<1, 0, 0><<<dim3(2, 32, 16), 256>>>(k_pass, kv_b, kcat, SQ, NOPE, KVL,
                                               KVL, KVL, KC,
                                               0L, (long)(NOPE + VDIM) * KVL, (long)SQ * KC);
    // 7. kcat cols 128:192 = k_rot
    krot_kernel<<<(int)(((long)NH * SQ * ROPE + 255) / 256), 256>>>(k_rot, kcat);
    // 8. v_eff[h] = k_pass @ v_b[h]^T   (batched z=16)
    sgemm_k<1, 0, 0><<<dim3(2, 32, 16), 256>>>(k_pass, kv_b + NOPE * KVL, ve, SQ, VDIM, KVL,
                                               KVL, KVL, VDIM,
                                               0L, (long)(NOPE + VDIM) * KVL, (long)SQ * VDIM);
    // 9. qcat = [q_pass, q_rot] per head
    qcat_kernel<<<(int)(((long)NH * SQ * KC + 255) / 256), 256>>>(q_pass, q_rot, qcat);
    // 10. indexer scores + top-k mask
    idx_score_kernel<<<dim3(64, 64), 256>>>(iq, ik, w, score);
    topk_kernel<<<SQ, 256>>>(score, mask);
    // 11. logits[h] = qcat[h] @ kcat[h]^T   (K=192, causal-N skip)
    sgemm_k<1, 1, 0><<<dim3(32, 32, 16), 256>>>(qcat, kcat, P, SQ, SQ, KC,
                                                KC, KC, SQ,
                                                (long)SQ * KC, (long)SQ * KC, (long)SQ * SQ);
    // 12. masked softmax
    softmax_kernel<<<dim3(SQ, NH), 256>>>(P, mask);
    // 13. out[s, h, :] = P[h] @ v_eff[h]   (causal-K limit, direct to output)
    sgemm_k<0, 0, 1><<<dim3(2, 32, 16), 256>>>(P, ve, out, SQ, VDIM, SQ,
                                               SQ, VDIM, NH * VDIM,
                                               (long)SQ * SQ, (long)SQ * VDIM, (long)VDIM);
}

// round 9
// speedup vs baseline: 1.6745x; 1.0557x over previous
#include <cuda_runtime.h>
#include <math.h>

#define SQ 2048
#define NH 16
#define ID 128
#define ROPE 64
#define NOPE 128
#define VDIM 128
#define KVL 512
#define KC 192          /* compressed logit K-dim: NOPE + ROPE */
#define HIDD 2048
#define QLORA 1536
#define TOPKK 1024
#define EPSV 1e-6f
#define SCALV 0.08838834764831845f  /* 128^-0.5 */

// ---------------- scratch (device globals; no runtime allocation) ----------------
__device__ float g_ckv[SQ * ID];
__device__ float g_ik[SQ * ID];
__device__ float g_ql[SQ * NH * ID];
__device__ float g_iq[SQ * NH * ID];
__device__ float g_wt[SQ * NH];
__device__ float g_w[SQ * NH];
__device__ float g_qcat[(size_t)NH * SQ * KC];   // [q_pass, q_rot] per head
__device__ float g_kcat[(size_t)NH * SQ * KC];   // [k_eff,  k_rot] per head
__device__ float g_ve[(size_t)NH * SQ * VDIM];   // v_eff per head
__device__ float g_score[SQ * SQ];
__device__ unsigned char g_mask[SQ * SQ];
__device__ float g_P[(size_t)NH * SQ * SQ];

// ---------------- SGEMM v2: 128x64 tile, 8x4 micro, double-buffered smem ----------------
// C = A @ B(^T). A: M x K row-major. TRANSB: B is N x K; else K x N.
// Requires: M % 128 == 0, K % 16 == 0 (holds for every call site here). N guarded.
template <int TRANSB, int CAUSAL_N, int CAUSAL_K>
__global__ __launch_bounds__(256) void sgemm2(
        const float* __restrict__ Ag, const float* __restrict__ Bg,
        float* __restrict__ Cg, int M, int N, int K,
        int lda, int ldb, int ldc, long aB, long bB, long cB) {
    constexpr int BM = 128, BN = 64, BK = 16;
    int bm = blockIdx.y, bn = blockIdx.x;
    if (CAUSAL_N && bn * BN > bm * BM + BM - 1) return;
    const float* A = Ag + (long)blockIdx.z * aB;
    const float* B = Bg + (long)blockIdx.z * bB;
    float* C = Cg + (long)blockIdx.z * cB;
    __shared__ float As[2][BK][BM];
    __shared__ float Bs[2][BK][BN];
    const int tid = threadIdx.x;
    const int tx = tid & 15, ty = tid >> 4;
    const int ar = tid >> 1, ac = (tid & 1) * 8;
    const int br = TRANSB ? (tid >> 2) : (tid >> 4);
    const int bc = TRANSB ? ((tid & 3) * 4) : ((tid & 15) * 4);

    float acc[8][4];
#pragma unroll
    for (int i = 0; i < 8; i++)
#pragma unroll
        for (int j = 0; j < 4; j++) acc[i][j] = 0.f;

    int kEnd = CAUSAL_K ? min(K, bm * BM + BM) : K;
    int nT = kEnd >> 4;

    const float* aPtr = A + (long)(bm * BM + ar) * lda + ac;

    // prologue: tile 0 -> smem[0]
    {
        float4 a0 = *(const float4*)(aPtr);
        float4 a1 = *(const float4*)(aPtr + 4);
        As[0][ac + 0][ar] = a0.x; As[0][ac + 1][ar] = a0.y;
        As[0][ac + 2][ar] = a0.z; As[0][ac + 3][ar] = a0.w;
        As[0][ac + 4][ar] = a1.x; As[0][ac + 5][ar] = a1.y;
        As[0][ac + 6][ar] = a1.z; As[0][ac + 7][ar] = a1.w;
        float4 bv = make_float4(0.f, 0.f, 0.f, 0.f);
        if (TRANSB) {
            int brow = bn * BN + br;
            if (brow < N) bv = *(const float4*)(B + (long)brow * ldb + bc);
            Bs[0][bc + 0][br] = bv.x; Bs[0][bc + 1][br] = bv.y;
            Bs[0][bc + 2][br] = bv.z; Bs[0][bc + 3][br] = bv.w;
        } else {
            int bcol = bn * BN + bc;
            if (bcol < N) bv = *(const float4*)(B + (long)br * ldb + bcol);
            *(float4*)&Bs[0][br][bc] = bv;
        }
    }
    __syncthreads();

    for (int t = 0; t < nT; t++) {
        int cur = t & 1;
        float4 pa0, pa1, pbv;
        bool has = (t + 1 < nT);
        if (has) {
            int k0 = (t + 1) << 4;
            pa0 = *(const float4*)(aPtr + k0);
            pa1 = *(const float4*)(aPtr + k0 + 4);
            pbv = make_float4(0.f, 0.f, 0.f, 0.f);
            if (TRANSB) {
                int brow = bn * BN + br;
                if (brow < N) pbv = *(const float4*)(B + (long)brow * ldb + k0 + bc);
            } else {
                int bcol = bn * BN + bc;
                if (bcol < N) pbv = *(const float4*)(B + (long)(k0 + br) * ldb + bcol);
            }
        }
#pragma unroll
        for (int kk = 0; kk < BK; kk++) {
            float4 a0 = *(const float4*)&As[cur][kk][ty * 8];
            float4 a1 = *(const float4*)&As[cur][kk][ty * 8 + 4];
            float4 b4 = *(const float4*)&Bs[cur][kk][tx * 4];
            float av[8] = {a0.x, a0.y, a0.z, a0.w, a1.x, a1.y, a1.z, a1.w};
            float bv2[4] = {b4.x, b4.y, b4.z, b4.w};
#pragma unroll
            for (int i = 0; i < 8; i++)
#pragma unroll
                for (int j = 0; j < 4; j++) acc[i][j] += av[i] * bv2[j];
        }
        if (has) {
            int nxt = cur ^ 1;
            As[nxt][ac + 0][ar] = pa0.x; As[nxt][ac + 1][ar] = pa0.y;
            As[nxt][ac + 2][ar] = pa0.z; As[nxt][ac + 3][ar] = pa0.w;
            As[nxt][ac + 4][ar] = pa1.x; As[nxt][ac + 5][ar] = pa1.y;
            As[nxt][ac + 6][ar] = pa1.z; As[nxt][ac + 7][ar] = pa1.w;
            if (TRANSB) {
                Bs[nxt][bc + 0][br] = pbv.x; Bs[nxt][bc + 1][br] = pbv.y;
                Bs[nxt][bc + 2][br] = pbv.z; Bs[nxt][bc + 3][br] = pbv.w;
            } else {
                *(float4*)&Bs[nxt][br][bc] = pbv;
            }
            __syncthreads();
        }
    }
#pragma unroll
    for (int i = 0; i < 8; i++) {
        int row = bm * BM + ty * 8 + i;
        float* cp = C + (long)row * ldc + bn * BN + tx * 4;
#pragma unroll
        for (int j = 0; j < 4; j++) {
            if (bn * BN + tx * 4 + j < N) cp[j] = acc[i][j];
        }
    }
}

// ---------------- index_k: rope(interleaved) + rmsnorm ----------------
__global__ void indexk_kernel(const float* __restrict__ ckv, const float* __restrict__ cosb,
                              const float* __restrict__ sinb, const float* __restrict__ knorm,
                              float* __restrict__ ik) {
    int s = blockIdx.x, j = threadIdx.x;  // 128 threads
    __shared__ float sh[128];
    __shared__ float red[128];
    sh[j] = ckv[s * 128 + j];
    __syncthreads();
    float x = (j >= 64) ? sh[j] * sh[j] : 0.f;
    red[j] = x;
    __syncthreads();
    for (int t = 64; t > 0; t >>= 1) {
        if (j < t) red[j] += red[j + t];
        __syncthreads();
    }
    float rstd = rsqrtf(red[0] / 64.f + EPSV);
    float o;
    if (j < 64) {
        float c = cosb[s * 64 + j], si = sinb[s * 64 + j];
        int jj = j & 31;
        float e = sh[2 * jj], od = sh[2 * jj + 1];
        o = (j < 32) ? (e * c - od * si) : (od * c + e * si);
    } else {
        o = sh[j] * rstd * knorm[j - 64];
    }
    ik[s * 128 + j] = o;
}

// ---------------- index_q: rope first 64 of each 128-chunk ----------------
__global__ void indexq_kernel(const float* __restrict__ ql, const float* __restrict__ cosb,
                              const float* __restrict__ sinb, float* __restrict__ iq) {
    int s = blockIdx.x;
    int tid = threadIdx.x;  // 256
    __shared__ float sh[2048];
    for (int i = tid; i < 2048; i += 256) sh[i] = ql[(long)s * 2048 + i];
    __syncthreads();
    for (int i = tid; i < 2048; i += 256) {
        int h = i >> 7, j = i & 127;
        float o;
        if (j < 64) {
            int jj = j & 31;
            float c = cosb[s * 64 + j], si = sinb[s * 64 + j];
            float e = sh[h * 128 + 2 * jj], od = sh[h * 128 + 2 * jj + 1];
            o = (j < 32) ? (e * c - od * si) : (od * c + e * si);
        } else {
            o = sh[h * 128 + j];
        }
        iq[(long)s * 2048 + i] = o;
    }
}

__global__ void absbias_kernel(const float* __restrict__ wt, const float* __restrict__ b,
                               float* __restrict__ w) {
    int i = blockIdx.x * 256 + threadIdx.x;
    if (i < SQ * NH) w[i] = fabsf(wt[i] + b[i & 15]);
}

// qcat[h][s][0:128] = q_pass[h][s], qcat[h][s][128:192] = q_rot[h][s]
__global__ void qcat_kernel(const float* __restrict__ qp, const float* __restrict__ qr,
                            float* __restrict__ qc) {
    long i = (long)blockIdx.x * 256 + threadIdx.x;
    if (i >= (long)NH * SQ * KC) return;
    int d = (int)(i % KC);
    long r = i / KC;
    int s = (int)(r % SQ);
    int h = (int)(r / SQ);
    qc[i] = (d < NOPE) ? qp[((long)h * SQ + s) * NOPE + d]
                       : qr[((long)h * SQ + s) * ROPE + (d - NOPE)];
}

// kcat[h][k][128:192] = k_rot[k]   (cols 0:128 filled by the k_eff GEMM)
__global__ void krot_kernel(const float* __restrict__ kr, float* __restrict__ kc) {
    long i = (long)blockIdx.x * 256 + threadIdx.x;
    if (i >= (long)NH * SQ * ROPE) return;
    int j = (int)(i % ROPE);
    long r = i / ROPE;
    int s = (int)(r % SQ);
    int h = (int)(r / SQ);
    kc[((long)h * SQ + s) * KC + NOPE + j] = kr[s * ROPE + j];
}

// ---------------- indexer score v2: 32x32 tile, 64 thr, 4x4 micro, float4 smem ----------------
__global__ __launch_bounds__(64) void idx_score2(const float* __restrict__ iq,
                                                 const float* __restrict__ ik,
                                                 const float* __restrict__ w,
                                                 float* __restrict__ score) {
    int bq = blockIdx.y, bk = blockIdx.x;
    if (bk > bq) return;  // strictly-above-diagonal 32-tiles never read
    __shared__ float iqs[32][132];
    __shared__ float iks[32][132];
    __shared__ float ws[16][32];
    int t = threadIdx.x;
#pragma unroll
    for (int c = 0; c < 16; c++) {
        int chunk = t + 64 * c;
        int c4 = chunk & 31, r = chunk >> 5;
        float4 v = *(const float4*)&ik[(bk * 32 + r) * 128 + c4 * 4];
        *(float4*)&iks[r][c4 * 4] = v;
    }
    for (int i = t; i < 512; i += 64) {
        int r = i >> 4, h = i & 15;
        ws[h][r] = w[(bq * 32 + r) * 16 + h];
    }
    int tq = t >> 3, tk = t & 7;
    float sacc[4][4];
#pragma unroll
    for (int i = 0; i < 4; i++)
#pragma unroll
        for (int j = 0; j < 4; j++) sacc[i][j] = 0.f;

    for (int h = 0; h < 16; h++) {
        __syncthreads();
#pragma unroll
        for (int c = 0; c < 16; c++) {
            int chunk = t + 64 * c;
            int c4 = chunk & 31, r = chunk >> 5;
            float4 v = *(const float4*)&iq[((long)(bq * 32 + r) * 16 + h) * 128 + c4 * 4];
            *(float4*)&iqs[r][c4 * 4] = v;
        }
        __syncthreads();
        float d[4][4];
#pragma unroll
        for (int i = 0; i < 4; i++)
#pragma unroll
            for (int j = 0; j < 4; j++) d[i][j] = 0.f;
#pragma unroll 4
        for (int c4 = 0; c4 < 32; c4++) {
            float4 A4[4], B4[4];
#pragma unroll
            for (int i = 0; i < 4; i++) A4[i] = *(const float4*)&iqs[tq * 4 + i][c4 * 4];
#pragma unroll
            for (int j = 0; j < 4; j++) B4[j] = *(const float4*)&iks[tk * 4 + j][c4 * 4];
#pragma unroll
            for (int i = 0; i < 4; i++)
#pragma unroll
                for (int j = 0; j < 4; j++)
                    d[i][j] += A4[i].x * B4[j].x + A4[i].y * B4[j].y +
                               A4[i].z * B4[j].z + A4[i].w * B4[j].w;
        }
#pragma unroll
        for (int i = 0; i < 4; i++) {
            float wv = ws[h][tq * 4 + i];
#pragma unroll
            for (int j = 0; j < 4; j++) sacc[i][j] += wv * fmaxf(d[i][j], 0.f);
        }
    }
#pragma unroll
    for (int i = 0; i < 4; i++) {
        long row = (long)(bq * 32 + tq * 4 + i);
        float4 o = make_float4(sacc[i][0] * SCALV, sacc[i][1] * SCALV,
                               sacc[i][2] * SCALV, sacc[i][3] * SCALV);
        *(float4*)&score[row * SQ + bk * 32 + tk * 4] = o;
    }
}

// ---------------- per-query top-1024 via radix select ----------------
__global__ void topk_kernel(const float* __restrict__ score, unsigned char* __restrict__ mask) {
    int q = blockIdx.x;
    int n = q + 1;
    int tid = threadIdx.x;  // 256
    unsigned char* mrow = mask + (long)q * SQ;
    if (q < TOPKK) {
        for (int k = tid; k < SQ; k += 256) mrow[k] = (k <= q) ? 1 : 0;
        return;
    }
    const float* srow = score + (long)q * SQ;
    __shared__ unsigned int sbits[SQ];
    __shared__ int hist[256];
    __shared__ unsigned int sh_prefix;
    __shared__ int sh_kk;
    for (int k = tid; k < n; k += 256) sbits[k] = __float_as_uint(srow[k]);
    if (tid == 0) { sh_prefix = 0u; sh_kk = TOPKK; }
    __syncthreads();
    for (int pass = 0; pass < 4; pass++) {
        int shift = 24 - 8 * pass;
        if (tid < 256) hist[tid] = 0;
        __syncthreads();
        unsigned int pfx = sh_prefix;
        for (int k = tid; k < n; k += 256) {
            unsigned int v = sbits[k];
            if ((unsigned int)(((unsigned long long)v) >> (shift + 8)) == pfx)
                atomicAdd(&hist[(v >> shift) & 255], 1);
        }
        __syncthreads();
        if (tid == 0) {
            int kk = sh_kk;
            int d = 255;
            for (; d >= 0; d--) {
                if (kk <= hist[d]) break;
                kk -= hist[d];
            }
            sh_prefix = (pfx << 8) | (unsigned int)d;
            sh_kk = kk;
        }
        __syncthreads();
    }
    unsigned int T = sh_prefix;
    int kk = sh_kk;
    for (int k = tid; k < SQ; k += 256) {
        unsigned char m = 0;
        if (k < n) {
            unsigned int v = sbits[k];
            if (v > T) m = 1;
            else if (v == T) {
                int rank = 0;
                for (int j = 0; j < k; j++) rank += (sbits[j] == T) ? 1 : 0;
                m = (rank < kk) ? 1 : 0;
            }
        }
        mrow[k] = m;
    }
}

// ---------------- masked softmax (causal-bounded: only k < kLim touched) ----------------
// AV GEMM (CAUSAL_K) only reads k < (q/128+1)*128, which logits (CAUSAL_N) fully computed.
__global__ void softmax2(float* __restrict__ P, const unsigned char* __restrict__ mask) {
    int q = blockIdx.x, h = blockIdx.y;
    int n = (q & ~127) + 128;  // kLim
    float* row = P + ((long)h * SQ + q) * SQ;
    const unsigned char* mrow = mask + (long)q * SQ;
    int tid = threadIdx.x;  // 256
    float v[8];
    float mx = -1e30f;
#pragma unroll
    for (int i = 0; i < 8; i++) {
        int k = i * 256 + tid;
        float val = -1e30f;
        if (k < n && mrow[k]) val = row[k] * SCALV;
        v[i] = val;
        mx = fmaxf(mx, val);
    }
    __shared__ float red[256];
    red[tid] = mx;
    __syncthreads();
    for (int s = 128; s > 0; s >>= 1) {
        if (tid < s) red[tid] = fmaxf(red[tid], red[tid + s]);
        __syncthreads();
    }
    mx = red[0];
    __syncthreads();
    float sum = 0.f;
#pragma unroll
    for (int i = 0; i < 8; i++) {
        float e = (v[i] > -1e29f) ? __expf(v[i] - mx) : 0.f;
        v[i] = e;
        sum += e;
    }
    red[tid] = sum;
    __syncthreads();
    for (int s = 128; s > 0; s >>= 1) {
        if (tid < s) red[tid] += red[tid + s];
        __syncthreads();
    }
    float inv = 1.f / red[0];
#pragma unroll
    for (int i = 0; i < 8; i++) {
        int k = i * 256 + tid;
        if (k < n) row[k] = v[i] * inv;
    }
}

// ---------------- launch ----------------
extern "C" void kernel_launch(void* const* d_in, const int* in_sizes, int n_in,
                              void* d_out, int out_size) {
    const float* q_latent = (const float*)d_in[0];
    const float* hidden   = (const float*)d_in[1];
    const float* cosb     = (const float*)d_in[2];
    const float* sinb     = (const float*)d_in[3];
    const float* q_pass   = (const float*)d_in[4];
    const float* q_rot    = (const float*)d_in[5];
    const float* k_pass   = (const float*)d_in[6];
    const float* k_rot    = (const float*)d_in[7];
    /* d_in[8] = position_ids (unused) */
    const float* kv_b     = (const float*)d_in[9];
    const float* wq_b     = (const float*)d_in[10];
    const float* wk       = (const float*)d_in[11];
    const float* knorm    = (const float*)d_in[12];
    const float* wproj    = (const float*)d_in[13];
    const float* wproj_b  = (const float*)d_in[14];
    float* out = (float*)d_out;

    float *ckv, *ik, *ql, *iq, *wt, *w, *qcat, *kcat, *ve, *score, *P;
    unsigned char* mask;
    cudaGetSymbolAddress((void**)&ckv, g_ckv);
    cudaGetSymbolAddress((void**)&ik, g_ik);
    cudaGetSymbolAddress((void**)&ql, g_ql);
    cudaGetSymbolAddress((void**)&iq, g_iq);
    cudaGetSymbolAddress((void**)&wt, g_wt);
    cudaGetSymbolAddress((void**)&w, g_w);
    cudaGetSymbolAddress((void**)&qcat, g_qcat);
    cudaGetSymbolAddress((void**)&kcat, g_kcat);
    cudaGetSymbolAddress((void**)&ve, g_ve);
    cudaGetSymbolAddress((void**)&score, g_score);
    cudaGetSymbolAddress((void**)&mask, g_mask);
    cudaGetSymbolAddress((void**)&P, g_P);

    // 1. ckv = hidden @ wk^T   (2048x128)
    sgemm2<1, 0, 0><<<dim3(2, 16, 1), 256>>>(hidden, wk, ckv, SQ, ID, HIDD,
                                             HIDD, HIDD, ID, 0, 0, 0);
    // 2. index_k
    indexk_kernel<<<SQ, 128>>>(ckv, cosb, sinb, knorm, ik);
    // 3. ql = q_latent @ wq_b^T   (2048x2048)
    sgemm2<1, 0, 0><<<dim3(32, 16, 1), 256>>>(q_latent, wq_b, ql, SQ, NH * ID, QLORA,
                                              QLORA, QLORA, NH * ID, 0, 0, 0);
    // 4. index_q
    indexq_kernel<<<SQ, 256>>>(ql, cosb, sinb, iq);
    // 5. w = |hidden @ wproj^T + b|
    sgemm2<1, 0, 0><<<dim3(1, 16, 1), 256>>>(hidden, wproj, wt, SQ, NH, HIDD,
                                             HIDD, HIDD, NH, 0, 0, 0);
    absbias_kernel<<<(SQ * NH + 255) / 256, 256>>>(wt, wproj_b, w);
    // 6. k_eff[h] = k_pass @ k_b[h]^T  -> kcat cols 0:128  (batched z=16)
    sgemm2<1, 0, 0><<<dim3(2, 16, 16), 256>>>(k_pass, kv_b, kcat, SQ, NOPE, KVL,
                                              KVL, KVL, KC,
                                              0L, (long)(NOPE + VDIM) * KVL, (long)SQ * KC);
    // 7. kcat cols 128:192 = k_rot
    krot_kernel<<<(int)(((long)NH * SQ * ROPE + 255) / 256), 256>>>(k_rot, kcat);
    // 8. v_eff[h] = k_pass @ v_b[h]^T   (batched z=16)
    sgemm2<1, 0, 0><<<dim3(2, 16, 16), 256>>>(k_pass, kv_b + NOPE * KVL, ve, SQ, VDIM, KVL,
                                              KVL, KVL, VDIM,
                                              0L, (long)(NOPE + VDIM) * KVL, (long)SQ * VDIM);
    // 9. qcat = [q_pass, q_rot] per head
    qcat_kernel<<<(int)(((long)NH * SQ * KC + 255) / 256), 256>>>(q_pass, q_rot, qcat);
    // 10. indexer scores + top-k mask
    idx_score2<<<dim3(64, 64), 64>>>(iq, ik, w, score);
    topk_kernel<<<SQ, 256>>>(score, mask);
    // 11. logits[h] = qcat[h] @ kcat[h]^T   (K=192, causal-N skip)
    sgemm2<1, 1, 0><<<dim3(32, 16, 16), 256>>>(qcat, kcat, P, SQ, SQ, KC,
                                               KC, KC, SQ,
                                               (long)SQ * KC, (long)SQ * KC, (long)SQ * SQ);
    // 12. masked softmax (causal-bounded)
    softmax2<<<dim3(SQ, NH), 256>>>(P, mask);
    // 13. out[s, h, :] = P[h] @ v_eff[h]   (causal-K limit, direct to output)
    sgemm2<0, 0, 1><<<dim3(2, 16, 16), 256>>>(P, ve, out, SQ, VDIM, SQ,
                                              SQ, VDIM, NH * VDIM,
                                              (long)SQ * SQ, (long)SQ * VDIM, (long)VDIM);
}

// round 14
// speedup vs baseline: 2.0927x; 1.2497x over previous
#include <cuda_runtime.h>
#include <cuda_bf16.h>
#include <math.h>

#define SQ 2048
#define NH 16
#define ID 128
#define ROPE 64
#define NOPE 128
#define VDIM 128
#define KVL 512
#define KC 192          /* compressed logit K-dim: NOPE + ROPE */
#define HIDD 2048
#define QLORA 1536
#define TOPKK 1024
#define EPSV 1e-6f
#define SCALV 0.08838834764831845f  /* 128^-0.5 */

typedef __nv_bfloat16 bf16;

// ---------------- scratch (device globals; no runtime allocation) ----------------
__device__ float g_ckv[SQ * ID];
__device__ float g_ik[SQ * ID];
__device__ float g_ql[SQ * NH * ID];
__device__ float g_iq[SQ * NH * ID];
__device__ float g_wt[SQ * NH];
__device__ float g_w[SQ * NH];
__device__ float g_score[SQ * SQ];
__device__ unsigned char g_mask[SQ * SQ];
__device__ float g_P[(size_t)NH * SQ * SQ];

// bf16 hi/lo split buffers (smooth-path GEMMs only; selection path stays fp32)
__device__ bf16 g_kp_h[SQ * KVL],    g_kp_l[SQ * KVL];
__device__ bf16 g_kvb_h[NH * (NOPE + VDIM) * KVL], g_kvb_l[NH * (NOPE + VDIM) * KVL];
__device__ bf16 g_qcat_h[(size_t)NH * SQ * KC], g_qcat_l[(size_t)NH * SQ * KC];
__device__ bf16 g_kcat_h[(size_t)NH * SQ * KC], g_kcat_l[(size_t)NH * SQ * KC];
__device__ bf16 g_ve_h[(size_t)NH * SQ * VDIM], g_ve_l[(size_t)NH * SQ * VDIM];
__device__ bf16 g_Ph[(size_t)NH * SQ * SQ], g_Pl[(size_t)NH * SQ * SQ];

// ---------------- helpers ----------------
__device__ __forceinline__ unsigned smem_u32(const void* p) {
    return (unsigned)__cvta_generic_to_shared(p);
}
__device__ __forceinline__ void split1(float x, bf16& h, bf16& l) {
    h = __float2bfloat16(x);
    l = __float2bfloat16(x - __bfloat162float(h));
}
__device__ __forceinline__ void ldsm_x4(unsigned& r0, unsigned& r1, unsigned& r2, unsigned& r3,
                                        unsigned addr) {
    asm volatile("ldmatrix.sync.aligned.m8n8.x4.shared.b16 {%0,%1,%2,%3},[%4];"
                 : "=r"(r0), "=r"(r1), "=r"(r2), "=r"(r3) : "r"(addr));
}
__device__ __forceinline__ void ldsm_x4_t(unsigned& r0, unsigned& r1, unsigned& r2, unsigned& r3,
                                          unsigned addr) {
    asm volatile("ldmatrix.sync.aligned.m8n8.x4.trans.shared.b16 {%0,%1,%2,%3},[%4];"
                 : "=r"(r0), "=r"(r1), "=r"(r2), "=r"(r3) : "r"(addr));
}
__device__ __forceinline__ void mma_bf16(float* c, const unsigned* a, const unsigned* b) {
    asm volatile(
        "mma.sync.aligned.m16n8k16.row.col.f32.bf16.bf16.f32 "
        "{%0,%1,%2,%3},{%4,%5,%6,%7},{%8,%9},{%0,%1,%2,%3};"
        : "+f"(c[0]), "+f"(c[1]), "+f"(c[2]), "+f"(c[3])
        : "r"(a[0]), "r"(a[1]), "r"(a[2]), "r"(a[3]), "r"(b[0]), "r"(b[1]));
}

// ---------------- bf16 hi/lo tensor GEMM ----------------
// C = A @ B(^T) with A = Ahi+Alo, B = Bhi+Blo (3-term product, fp32 accumulate).
// A: M x K bf16 row-major. TRANSB: B is N x K; else K x N.
// BM=128, BN=64, BK=32. 256 threads = 8 warps (4x2), warp tile 32x32.
// Requires K % 32 == 0, N % 64 == 0, M % 128 == 0 (all call sites satisfy).
template <int TRANSB, int CAUSAL_N, int CAUSAL_K, int SPLIT_OUT>
__global__ __launch_bounds__(256) void hgemm(
        const bf16* __restrict__ Ahig, const bf16* __restrict__ Alog,
        const bf16* __restrict__ Bhig, const bf16* __restrict__ Blog,
        float* __restrict__ Cg, bf16* __restrict__ Chig, bf16* __restrict__ Clog,
        int N, int K, int lda, int ldb, int ldc, long aB, long bB, long cB) {
    constexpr int BM = 128, BN = 64, BK = 32;
    constexpr int BROWS = TRANSB ? 64 : 32;
    constexpr int BSTR = TRANSB ? 40 : 72;
    int bm = blockIdx.y, bn = blockIdx.x;
    if (CAUSAL_N && bn * BN > bm * BM + BM - 1) return;
    long z = blockIdx.z;
    const bf16* Ahi = Ahig + z * aB;
    const bf16* Alo = Alog + z * aB;
    const bf16* Bhi = Bhig + z * bB;
    const bf16* Blo = Blog + z * bB;

    __shared__ __align__(16) bf16 As[2][BM * 40];
    __shared__ __align__(16) bf16 Bs[2][BROWS * BSTR];

    int tid = threadIdx.x, lane = tid & 31, warp = tid >> 5;
    int wm = warp >> 1, wn = warp & 1;

    float acc[2][4][4];
#pragma unroll
    for (int i = 0; i < 2; i++)
#pragma unroll
        for (int j = 0; j < 4; j++)
#pragma unroll
            for (int k = 0; k < 4; k++) acc[i][j][k] = 0.f;

    int kEnd = CAUSAL_K ? (bm * BM + BM < K ? bm * BM + BM : K) : K;

    // A tile: 128 rows x 32 cols bf16 = 512 uint4 per buffer; 256 thr -> 2 uint4/thr/buf.
    const int arow = tid >> 1, acol = (tid & 1) * 16;
    const bf16* aph = Ahi + (long)(bm * BM + arow) * lda + acol;
    const bf16* apl = Alo + (long)(bm * BM + arow) * lda + acol;
    const bf16 *bph, *bpl;
    int brow, bcol;
    if (TRANSB) {
        brow = tid >> 2; bcol = (tid & 3) * 8;
        bph = Bhi + (long)(bn * BN + brow) * ldb + bcol;
        bpl = Blo + (long)(bn * BN + brow) * ldb + bcol;
    } else {
        brow = tid >> 3; bcol = (tid & 7) * 8;
        bph = Bhi + (long)brow * ldb + bn * BN + bcol;
        bpl = Blo + (long)brow * ldb + bn * BN + bcol;
    }

    for (int k0 = 0; k0 < kEnd; k0 += BK) {
        uint4 vah0 = *(const uint4*)(aph + k0);
        uint4 vah1 = *(const uint4*)(aph + k0 + 8);
        uint4 val0 = *(const uint4*)(apl + k0);
        uint4 val1 = *(const uint4*)(apl + k0 + 8);
        uint4 vbh, vbl;
        if (TRANSB) {
            vbh = *(const uint4*)(bph + k0);
            vbl = *(const uint4*)(bpl + k0);
        } else {
            vbh = *(const uint4*)(bph + (long)k0 * ldb);
            vbl = *(const uint4*)(bpl + (long)k0 * ldb);
        }
        __syncthreads();  // previous tile's reads done
        *(uint4*)&As[0][arow * 40 + acol] = vah0;
        *(uint4*)&As[0][arow * 40 + acol + 8] = vah1;
        *(uint4*)&As[1][arow * 40 + acol] = val0;
        *(uint4*)&As[1][arow * 40 + acol + 8] = val1;
        *(uint4*)&Bs[0][brow * BSTR + bcol] = vbh;
        *(uint4*)&Bs[1][brow * BSTR + bcol] = vbl;
        __syncthreads();

#pragma unroll
        for (int kk = 0; kk < BK; kk += 16) {
            unsigned ah[2][4], al[2][4];
#pragma unroll
            for (int mb = 0; mb < 2; mb++) {
                int r = wm * 32 + mb * 16 + (lane & 15);
                int c = kk + (lane >> 4) * 8;
                ldsm_x4(ah[mb][0], ah[mb][1], ah[mb][2], ah[mb][3],
                        smem_u32(&As[0][r * 40 + c]));
                ldsm_x4(al[mb][0], al[mb][1], al[mb][2], al[mb][3],
                        smem_u32(&As[1][r * 40 + c]));
            }
            unsigned bh[4][2], bl[4][2];
#pragma unroll
            for (int nb2 = 0; nb2 < 2; nb2++) {
                if (TRANSB) {
                    int n = wn * 32 + nb2 * 16 + (lane & 7) + ((lane >> 4) & 1) * 8;
                    int k = kk + ((lane >> 3) & 1) * 8;
                    ldsm_x4(bh[nb2 * 2][0], bh[nb2 * 2][1], bh[nb2 * 2 + 1][0], bh[nb2 * 2 + 1][1],
                            smem_u32(&Bs[0][n * BSTR + k]));
                    ldsm_x4(bl[nb2 * 2][0], bl[nb2 * 2][1], bl[nb2 * 2 + 1][0], bl[nb2 * 2 + 1][1],
                            smem_u32(&Bs[1][n * BSTR + k]));
                } else {
                    int k = kk + (lane & 7) + ((lane >> 3) & 1) * 8;
                    int n = wn * 32 + nb2 * 16 + ((lane >> 4) & 1) * 8;
                    ldsm_x4_t(bh[nb2 * 2][0], bh[nb2 * 2][1], bh[nb2 * 2 + 1][0], bh[nb2 * 2 + 1][1],
                              smem_u32(&Bs[0][k * BSTR + n]));
                    ldsm_x4_t(bl[nb2 * 2][0], bl[nb2 * 2][1], bl[nb2 * 2 + 1][0], bl[nb2 * 2 + 1][1],
                              smem_u32(&Bs[1][k * BSTR + n]));
                }
            }
#pragma unroll
            for (int mb = 0; mb < 2; mb++)
#pragma unroll
                for (int nb = 0; nb < 4; nb++) {
                    mma_bf16(acc[mb][nb], ah[mb], bh[nb]);  // hi*hi
                    mma_bf16(acc[mb][nb], ah[mb], bl[nb]);  // hi*lo
                    mma_bf16(acc[mb][nb], al[mb], bh[nb]);  // lo*hi
                }
        }
    }

    // epilogue
#pragma unroll
    for (int mb = 0; mb < 2; mb++) {
        int r = bm * BM + wm * 32 + mb * 16 + (lane >> 2);
#pragma unroll
        for (int nb = 0; nb < 4; nb++) {
            int c = bn * BN + wn * 32 + nb * 8 + (lane & 3) * 2;
            if (SPLIT_OUT) {
                bf16 h0, l0, h1, l1;
                split1(acc[mb][nb][0], h0, l0);
                split1(acc[mb][nb][1], h1, l1);
                *(__nv_bfloat162*)&Chig[z * cB + (long)r * ldc + c] = __nv_bfloat162(h0, h1);
                *(__nv_bfloat162*)&Clog[z * cB + (long)r * ldc + c] = __nv_bfloat162(l0, l1);
                split1(acc[mb][nb][2], h0, l0);
                split1(acc[mb][nb][3], h1, l1);
                *(__nv_bfloat162*)&Chig[z * cB + (long)(r + 8) * ldc + c] = __nv_bfloat162(h0, h1);
                *(__nv_bfloat162*)&Clog[z * cB + (long)(r + 8) * ldc + c] = __nv_bfloat162(l0, l1);
            } else {
                *(float2*)&Cg[z * cB + (long)r * ldc + c] =
                    make_float2(acc[mb][nb][0], acc[mb][nb][1]);
                *(float2*)&Cg[z * cB + (long)(r + 8) * ldc + c] =
                    make_float2(acc[mb][nb][2], acc[mb][nb][3]);
            }
        }
    }
}

// ---------------- fp32 SGEMM (selection path: exact) ----------------
template <int TRANSB, int CAUSAL_N, int CAUSAL_K>
__global__ __launch_bounds__(256) void sgemm2(
        const float* __restrict__ Ag, const float* __restrict__ Bg,
        float* __restrict__ Cg, int M, int N, int K,
        int lda, int ldb, int ldc, long aB, long bB, long cB) {
    constexpr int BM = 128, BN = 64, BK = 16;
    int bm = blockIdx.y, bn = blockIdx.x;
    if (CAUSAL_N && bn * BN > bm * BM + BM - 1) return;
    const float* A = Ag + (long)blockIdx.z * aB;
    const float* B = Bg + (long)blockIdx.z * bB;
    float* C = Cg + (long)blockIdx.z * cB;
    __shared__ float As[2][BK][BM];
    __shared__ float Bs[2][BK][BN];
    const int tid = threadIdx.x;
    const int tx = tid & 15, ty = tid >> 4;
    const int ar = tid >> 1, ac = (tid & 1) * 8;
    const int br = TRANSB ? (tid >> 2) : (tid >> 4);
    const int bc = TRANSB ? ((tid & 3) * 4) : ((tid & 15) * 4);
    float acc[8][4];
#pragma unroll
    for (int i = 0; i < 8; i++)
#pragma unroll
        for (int j = 0; j < 4; j++) acc[i][j] = 0.f;
    int kEnd = CAUSAL_K ? min(K, bm * BM + BM) : K;
    int nT = kEnd >> 4;
    const float* aPtr = A + (long)(bm * BM + ar) * lda + ac;
    {
        float4 a0 = *(const float4*)(aPtr);
        float4 a1 = *(const float4*)(aPtr + 4);
        As[0][ac + 0][ar] = a0.x; As[0][ac + 1][ar] = a0.y;
        As[0][ac + 2][ar] = a0.z; As[0][ac + 3][ar] = a0.w;
        As[0][ac + 4][ar] = a1.x; As[0][ac + 5][ar] = a1.y;
        As[0][ac + 6][ar] = a1.z; As[0][ac + 7][ar] = a1.w;
        float4 bv = make_float4(0.f, 0.f, 0.f, 0.f);
        if (TRANSB) {
            int brow = bn * BN + br;
            if (brow < N) bv = *(const float4*)(B + (long)brow * ldb + bc);
            Bs[0][bc + 0][br] = bv.x; Bs[0][bc + 1][br] = bv.y;
            Bs[0][bc + 2][br] = bv.z; Bs[0][bc + 3][br] = bv.w;
        } else {
            int bcol = bn * BN + bc;
            if (bcol < N) bv = *(const float4*)(B + (long)br * ldb + bcol);
            *(float4*)&Bs[0][br][bc] = bv;
        }
    }
    __syncthreads();
    for (int t = 0; t < nT; t++) {
        int cur = t & 1;
        float4 pa0, pa1, pbv;
        bool has = (t + 1 < nT);
        if (has) {
            int k0 = (t + 1) << 4;
            pa0 = *(const float4*)(aPtr + k0);
            pa1 = *(const float4*)(aPtr + k0 + 4);
            pbv = make_float4(0.f, 0.f, 0.f, 0.f);
            if (TRANSB) {
                int brow = bn * BN + br;
                if (brow < N) pbv = *(const float4*)(B + (long)brow * ldb + k0 + bc);
            } else {
                int bcol = bn * BN + bc;
                if (bcol < N) pbv = *(const float4*)(B + (long)(k0 + br) * ldb + bcol);
            }
        }
#pragma unroll
        for (int kk = 0; kk < BK; kk++) {
            float4 a0 = *(const float4*)&As[cur][kk][ty * 8];
            float4 a1 = *(const float4*)&As[cur][kk][ty * 8 + 4];
            float4 b4 = *(const float4*)&Bs[cur][kk][tx * 4];
            float av[8] = {a0.x, a0.y, a0.z, a0.w, a1.x, a1.y, a1.z, a1.w};
            float bv2[4] = {b4.x, b4.y, b4.z, b4.w};
#pragma unroll
            for (int i = 0; i < 8; i++)
#pragma unroll
                for (int j = 0; j < 4; j++) acc[i][j] += av[i] * bv2[j];
        }
        if (has) {
            int nxt = cur ^ 1;
            As[nxt][ac + 0][ar] = pa0.x; As[nxt][ac + 1][ar] = pa0.y;
            As[nxt][ac + 2][ar] = pa0.z; As[nxt][ac + 3][ar] = pa0.w;
            As[nxt][ac + 4][ar] = pa1.x; As[nxt][ac + 5][ar] = pa1.y;
            As[nxt][ac + 6][ar] = pa1.z; As[nxt][ac + 7][ar] = pa1.w;
            if (TRANSB) {
                Bs[nxt][bc + 0][br] = pbv.x; Bs[nxt][bc + 1][br] = pbv.y;
                Bs[nxt][bc + 2][br] = pbv.z; Bs[nxt][bc + 3][br] = pbv.w;
            } else {
                *(float4*)&Bs[nxt][br][bc] = pbv;
            }
            __syncthreads();
        }
    }
#pragma unroll
    for (int i = 0; i < 8; i++) {
        int row = bm * BM + ty * 8 + i;
        float* cp = C + (long)row * ldc + bn * BN + tx * 4;
#pragma unroll
        for (int j = 0; j < 4; j++) {
            if (bn * BN + tx * 4 + j < N) cp[j] = acc[i][j];
        }
    }
}

// ---------------- split kernels ----------------
__global__ void split_kernel(const float* __restrict__ x, bf16* __restrict__ h,
                             bf16* __restrict__ l, long n) {
    long i = ((long)blockIdx.x * 256 + threadIdx.x) * 4;
    if (i >= n) return;
    float4 v = *(const float4*)(x + i);
    bf16 h0, l0, h1, l1;
    split1(v.x, h0, l0); split1(v.y, h1, l1);
    *(__nv_bfloat162*)&h[i] = __nv_bfloat162(h0, h1);
    *(__nv_bfloat162*)&l[i] = __nv_bfloat162(l0, l1);
    split1(v.z, h0, l0); split1(v.w, h1, l1);
    *(__nv_bfloat162*)&h[i + 2] = __nv_bfloat162(h0, h1);
    *(__nv_bfloat162*)&l[i + 2] = __nv_bfloat162(l0, l1);
}

// ---------------- index_k: rope(interleaved) + rmsnorm ----------------
__global__ void indexk_kernel(const float* __restrict__ ckv, const float* __restrict__ cosb,
                              const float* __restrict__ sinb, const float* __restrict__ knorm,
                              float* __restrict__ ik) {
    int s = blockIdx.x, j = threadIdx.x;  // 128 threads
    __shared__ float sh[128];
    __shared__ float red[128];
    sh[j] = ckv[s * 128 + j];
    __syncthreads();
    float x = (j >= 64) ? sh[j] * sh[j] : 0.f;
    red[j] = x;
    __syncthreads();
    for (int t = 64; t > 0; t >>= 1) {
        if (j < t) red[j] += red[j + t];
        __syncthreads();
    }
    float rstd = rsqrtf(red[0] / 64.f + EPSV);
    float o;
    if (j < 64) {
        float c = cosb[s * 64 + j], si = sinb[s * 64 + j];
        int jj = j & 31;
        float e = sh[2 * jj], od = sh[2 * jj + 1];
        o = (j < 32) ? (e * c - od * si) : (od * c + e * si);
    } else {
        o = sh[j] * rstd * knorm[j - 64];
    }
    ik[s * 128 + j] = o;
}

// ---------------- index_q: rope first 64 of each 128-chunk ----------------
__global__ void indexq_kernel(const float* __restrict__ ql, const float* __restrict__ cosb,
                              const float* __restrict__ sinb, float* __restrict__ iq) {
    int s = blockIdx.x;
    int tid = threadIdx.x;  // 256
    __shared__ float sh[2048];
    for (int i = tid; i < 2048; i += 256) sh[i] = ql[(long)s * 2048 + i];
    __syncthreads();
    for (int i = tid; i < 2048; i += 256) {
        int h = i >> 7, j = i & 127;
        float o;
        if (j < 64) {
            int jj = j & 31;
            float c = cosb[s * 64 + j], si = sinb[s * 64 + j];
            float e = sh[h * 128 + 2 * jj], od = sh[h * 128 + 2 * jj + 1];
            o = (j < 32) ? (e * c - od * si) : (od * c + e * si);
        } else {
            o = sh[h * 128 + j];
        }
        iq[(long)s * 2048 + i] = o;
    }
}

__global__ void absbias_kernel(const float* __restrict__ wt, const float* __restrict__ b,
                               float* __restrict__ w) {
    int i = blockIdx.x * 256 + threadIdx.x;
    if (i < SQ * NH) w[i] = fabsf(wt[i] + b[i & 15]);
}

// qcat[h][s][0:128]=q_pass, [128:192]=q_rot, split to hi/lo
__global__ void qcat_split(const float* __restrict__ qp, const float* __restrict__ qr,
                           bf16* __restrict__ qh, bf16* __restrict__ qlo) {
    long i = (long)blockIdx.x * 256 + threadIdx.x;
    if (i >= (long)NH * SQ * KC) return;
    int d = (int)(i % KC);
    long r = i / KC;
    int s = (int)(r % SQ);
    int h = (int)(r / SQ);
    float v = (d < NOPE) ? qp[((long)h * SQ + s) * NOPE + d]
                         : qr[((long)h * SQ + s) * ROPE + (d - NOPE)];
    split1(v, qh[i], qlo[i]);
}

// kcat[h][k][128:192] = k_rot[k] split (cols 0:128 from k_eff GEMM epilogue)
__global__ void krot_split(const float* __restrict__ kr, bf16* __restrict__ kh,
                           bf16* __restrict__ kl) {
    long i = (long)blockIdx.x * 256 + threadIdx.x;
    if (i >= (long)NH * SQ * ROPE) return;
    int j = (int)(i % ROPE);
    long r = i / ROPE;
    int s = (int)(r % SQ);
    int h = (int)(r / SQ);
    long o = ((long)h * SQ + s) * KC + NOPE + j;
    split1(kr[s * ROPE + j], kh[o], kl[o]);
}

// ---------------- indexer score: 32x32 tile, 64 thr, 4x4 micro (fp32, exact) --------
__global__ __launch_bounds__(64) void idx_score2(const float* __restrict__ iq,
                                                 const float* __restrict__ ik,
                                                 const float* __restrict__ w,
                                                 float* __restrict__ score) {
    int bq = blockIdx.y, bk = blockIdx.x;
    if (bk > bq) return;
    __shared__ float iqs[32][132];
    __shared__ float iks[32][132];
    __shared__ float ws[16][32];
    int t = threadIdx.x;
#pragma unroll
    for (int c = 0; c < 16; c++) {
        int chunk = t + 64 * c;
        int c4 = chunk & 31, r = chunk >> 5;
        float4 v = *(const float4*)&ik[(bk * 32 + r) * 128 + c4 * 4];
        *(float4*)&iks[r][c4 * 4] = v;
    }
    for (int i = t; i < 512; i += 64) {
        int r = i >> 4, h = i & 15;
        ws[h][r] = w[(bq * 32 + r) * 16 + h];
    }
    int tq = t >> 3, tk = t & 7;
    float sacc[4][4];
#pragma unroll
    for (int i = 0; i < 4; i++)
#pragma unroll
        for (int j = 0; j < 4; j++) sacc[i][j] = 0.f;
    for (int h = 0; h < 16; h++) {
        __syncthreads();
#pragma unroll
        for (int c = 0; c < 16; c++) {
            int chunk = t + 64 * c;
            int c4 = chunk & 31, r = chunk >> 5;
            float4 v = *(const float4*)&iq[((long)(bq * 32 + r) * 16 + h) * 128 + c4 * 4];
            *(float4*)&iqs[r][c4 * 4] = v;
        }
        __syncthreads();
        float d[4][4];
#pragma unroll
        for (int i = 0; i < 4; i++)
#pragma unroll
            for (int j = 0; j < 4; j++) d[i][j] = 0.f;
#pragma unroll 4
        for (int c4 = 0; c4 < 32; c4++) {
            float4 A4[4], B4[4];
#pragma unroll
            for (int i = 0; i < 4; i++) A4[i] = *(const float4*)&iqs[tq * 4 + i][c4 * 4];
#pragma unroll
            for (int j = 0; j < 4; j++) B4[j] = *(const float4*)&iks[tk * 4 + j][c4 * 4];
#pragma unroll
            for (int i = 0; i < 4; i++)
#pragma unroll
                for (int j = 0; j < 4; j++)
                    d[i][j] += A4[i].x * B4[j].x + A4[i].y * B4[j].y +
                               A4[i].z * B4[j].z + A4[i].w * B4[j].w;
        }
#pragma unroll
        for (int i = 0; i < 4; i++) {
            float wv = ws[h][tq * 4 + i];
#pragma unroll
            for (int j = 0; j < 4; j++) sacc[i][j] += wv * fmaxf(d[i][j], 0.f);
        }
    }
#pragma unroll
    for (int i = 0; i < 4; i++) {
        long row = (long)(bq * 32 + tq * 4 + i);
        float4 o = make_float4(sacc[i][0] * SCALV, sacc[i][1] * SCALV,
                               sacc[i][2] * SCALV, sacc[i][3] * SCALV);
        *(float4*)&score[row * SQ + bk * 32 + tk * 4] = o;
    }
}

// ---------------- per-query top-1024 via radix select ----------------
__global__ void topk_kernel(const float* __restrict__ score, unsigned char* __restrict__ mask) {
    int q = blockIdx.x;
    int n = q + 1;
    int tid = threadIdx.x;  // 256
    unsigned char* mrow = mask + (long)q * SQ;
    if (q < TOPKK) {
        for (int k = tid; k < SQ; k += 256) mrow[k] = (k <= q) ? 1 : 0;
        return;
    }
    const float* srow = score + (long)q * SQ;
    __shared__ unsigned int sbits[SQ];
    __shared__ int hist[256];
    __shared__ unsigned int sh_prefix;
    __shared__ int sh_kk;
    for (int k = tid; k < n; k += 256) sbits[k] = __float_as_uint(srow[k]);
    if (tid == 0) { sh_prefix = 0u; sh_kk = TOPKK; }
    __syncthreads();
    for (int pass = 0; pass < 4; pass++) {
        int shift = 24 - 8 * pass;
        if (tid < 256) hist[tid] = 0;
        __syncthreads();
        unsigned int pfx = sh_prefix;
        for (int k = tid; k < n; k += 256) {
            unsigned int v = sbits[k];
            if ((unsigned int)(((unsigned long long)v) >> (shift + 8)) == pfx)
                atomicAdd(&hist[(v >> shift) & 255], 1);
        }
        __syncthreads();
        if (tid == 0) {
            int kk = sh_kk;
            int d = 255;
            for (; d >= 0; d--) {
                if (kk <= hist[d]) break;
                kk -= hist[d];
            }
            sh_prefix = (pfx << 8) | (unsigned int)d;
            sh_kk = kk;
        }
        __syncthreads();
    }
    unsigned int T = sh_prefix;
    int kk = sh_kk;
    for (int k = tid; k < SQ; k += 256) {
        unsigned char m = 0;
        if (k < n) {
            unsigned int v = sbits[k];
            if (v > T) m = 1;
            else if (v == T) {
                int rank = 0;
                for (int j = 0; j < k; j++) rank += (sbits[j] == T) ? 1 : 0;
                m = (rank < kk) ? 1 : 0;
            }
        }
        mrow[k] = m;
    }
}

// ---------------- masked softmax: reads fp32 logits, writes hi/lo bf16 probs --------
__global__ void softmax_split(const float* __restrict__ P, const unsigned char* __restrict__ mask,
                              bf16* __restrict__ Ph, bf16* __restrict__ Pl) {
    int q = blockIdx.x, h = blockIdx.y;
    int n = (q & ~127) + 128;  // kLim (AV only reads k < kLim)
    const float* row = P + ((long)h * SQ + q) * SQ;
    bf16* rh = Ph + ((long)h * SQ + q) * SQ;
    bf16* rl = Pl + ((long)h * SQ + q) * SQ;
    const unsigned char* mrow = mask + (long)q * SQ;
    int tid = threadIdx.x;  // 256
    float v[8];
    float mx = -1e30f;
#pragma unroll
    for (int i = 0; i < 8; i++) {
        int k = i * 256 + tid;
        float val = -1e30f;
        if (k < n && mrow[k]) val = row[k] * SCALV;
        v[i] = val;
        mx = fmaxf(mx, val);
    }
    __shared__ float red[256];
    red[tid] = mx;
    __syncthreads();
    for (int s = 128; s > 0; s >>= 1) {
        if (tid < s) red[tid] = fmaxf(red[tid], red[tid + s]);
        __syncthreads();
    }
    mx = red[0];
    __syncthreads();
    float sum = 0.f;
#pragma unroll
    for (int i = 0; i < 8; i++) {
        float e = (v[i] > -1e29f) ? __expf(v[i] - mx) : 0.f;
        v[i] = e;
        sum += e;
    }
    red[tid] = sum;
    __syncthreads();
    for (int s = 128; s > 0; s >>= 1) {
        if (tid < s) red[tid] += red[tid + s];
        __syncthreads();
    }
    float inv = 1.f / red[0];
#pragma unroll
    for (int i = 0; i < 8; i++) {
        int k = i * 256 + tid;
        if (k < n) {
            bf16 hh, ll;
            split1(v[i] * inv, hh, ll);
            rh[k] = hh;
            rl[k] = ll;
        }
    }
}

// ---------------- launch ----------------
extern "C" void kernel_launch(void* const* d_in, const int* in_sizes, int n_in,
                              void* d_out, int out_size) {
    const float* q_latent = (const float*)d_in[0];
    const float* hidden   = (const float*)d_in[1];
    const float* cosb     = (const float*)d_in[2];
    const float* sinb     = (const float*)d_in[3];
    const float* q_pass   = (const float*)d_in[4];
    const float* q_rot    = (const float*)d_in[5];
    const float* k_pass   = (const float*)d_in[6];
    const float* k_rot    = (const float*)d_in[7];
    /* d_in[8] = position_ids (unused) */
    const float* kv_b     = (const float*)d_in[9];
    const float* wq_b     = (const float*)d_in[10];
    const float* wk       = (const float*)d_in[11];
    const float* knorm    = (const float*)d_in[12];
    const float* wproj    = (const float*)d_in[13];
    const float* wproj_b  = (const float*)d_in[14];
    float* out = (float*)d_out;

    float *ckv, *ik, *ql, *iq, *wt, *w, *score, *P;
    unsigned char* mask;
    bf16 *kp_h, *kp_l, *kvb_h, *kvb_l, *qcat_h, *qcat_l, *kcat_h, *kcat_l;
    bf16 *ve_h, *ve_l, *Ph, *Pl;
    cudaGetSymbolAddress((void**)&ckv, g_ckv);
    cudaGetSymbolAddress((void**)&ik, g_ik);
    cudaGetSymbolAddress((void**)&ql, g_ql);
    cudaGetSymbolAddress((void**)&iq, g_iq);
    cudaGetSymbolAddress((void**)&wt, g_wt);
    cudaGetSymbolAddress((void**)&w, g_w);
    cudaGetSymbolAddress((void**)&score, g_score);
    cudaGetSymbolAddress((void**)&mask, g_mask);
    cudaGetSymbolAddress((void**)&P, g_P);
    cudaGetSymbolAddress((void**)&kp_h, g_kp_h);     cudaGetSymbolAddress((void**)&kp_l, g_kp_l);
    cudaGetSymbolAddress((void**)&kvb_h, g_kvb_h);   cudaGetSymbolAddress((void**)&kvb_l, g_kvb_l);
    cudaGetSymbolAddress((void**)&qcat_h, g_qcat_h); cudaGetSymbolAddress((void**)&qcat_l, g_qcat_l);
    cudaGetSymbolAddress((void**)&kcat_h, g_kcat_h); cudaGetSymbolAddress((void**)&kcat_l, g_kcat_l);
    cudaGetSymbolAddress((void**)&ve_h, g_ve_h);     cudaGetSymbolAddress((void**)&ve_l, g_ve_l);
    cudaGetSymbolAddress((void**)&Ph, g_Ph);         cudaGetSymbolAddress((void**)&Pl, g_Pl);

    // 0. splits of fp32 operands feeding SMOOTH-path tensor GEMMs only
    {
        long n;
        n = (long)SQ * KVL;        split_kernel<<<(int)(n / 4 / 256), 256>>>(k_pass, kp_h, kp_l, n);
        n = (long)NH * (NOPE + VDIM) * KVL;
                                   split_kernel<<<(int)(n / 4 / 256), 256>>>(kv_b, kvb_h, kvb_l, n);
    }
    // 1. ckv = hidden @ wk^T   (fp32 EXACT — feeds index_k -> top-k selection)
    sgemm2<1, 0, 0><<<dim3(2, 16, 1), 256>>>(hidden, wk, ckv, SQ, ID, HIDD,
                                             HIDD, HIDD, ID, 0, 0, 0);
    // 2. index_k
    indexk_kernel<<<SQ, 128>>>(ckv, cosb, sinb, knorm, ik);
    // 3. ql = q_latent @ wq_b^T   (fp32 EXACT — feeds index_q -> top-k selection)
    sgemm2<1, 0, 0><<<dim3(32, 16, 1), 256>>>(q_latent, wq_b, ql, SQ, NH * ID, QLORA,
                                              QLORA, QLORA, NH * ID, 0, 0, 0);
    // 4. index_q
    indexq_kernel<<<SQ, 256>>>(ql, cosb, sinb, iq);
    // 5. w = |hidden @ wproj^T + b|   (tiny fp32 GEMM)
    sgemm2<1, 0, 0><<<dim3(1, 16, 1), 256>>>(hidden, wproj, wt, SQ, NH, HIDD,
                                             HIDD, HIDD, NH, 0, 0, 0);
    absbias_kernel<<<(SQ * NH + 255) / 256, 256>>>(wt, wproj_b, w);
    // 6. k_eff[h] = k_pass @ k_b[h]^T -> kcat hi/lo cols 0:128  (tensor, SPLIT_OUT)
    hgemm<1, 0, 0, 1><<<dim3(2, 16, 16), 256>>>(kp_h, kp_l, kvb_h, kvb_l, nullptr, kcat_h, kcat_l,
                                                NOPE, KVL, KVL, KVL, KC,
                                                0L, (long)(NOPE + VDIM) * KVL, (long)SQ * KC);
    // 7. kcat cols 128:192 = k_rot (split)
    krot_split<<<(int)(((long)NH * SQ * ROPE + 255) / 256), 256>>>(k_rot, kcat_h, kcat_l);
    // 8. v_eff[h] = k_pass @ v_b[h]^T   (tensor, SPLIT_OUT)
    hgemm<1, 0, 0, 1><<<dim3(2, 16, 16), 256>>>(kp_h, kp_l, kvb_h + (long)NOPE * KVL,
                                                kvb_l + (long)NOPE * KVL, nullptr, ve_h, ve_l,
                                                VDIM, KVL, KVL, KVL, VDIM,
                                                0L, (long)(NOPE + VDIM) * KVL, (long)SQ * VDIM);
    // 9. qcat = [q_pass, q_rot] per head (split)
    qcat_split<<<(int)(((long)NH * SQ * KC + 255) / 256), 256>>>(q_pass, q_rot, qcat_h, qcat_l);
    // 10. indexer scores (fp32, exact) + top-k mask
    idx_score2<<<dim3(64, 64), 64>>>(iq, ik, w, score);
    topk_kernel<<<SQ, 256>>>(score, mask);
    // 11. logits[h] = qcat[h] @ kcat[h]^T   (tensor, K=192, causal-N skip)
    hgemm<1, 1, 0, 0><<<dim3(32, 16, 16), 256>>>(qcat_h, qcat_l, kcat_h, kcat_l, P, nullptr, nullptr,
                                                 SQ, KC, KC, KC, SQ,
                                                 (long)SQ * KC, (long)SQ * KC, (long)SQ * SQ);
    // 12. masked softmax -> P hi/lo bf16
    softmax_split<<<dim3(SQ, NH), 256>>>(P, mask, Ph, Pl);
    // 13. out[s, h, :] = P[h] @ v_eff[h]   (tensor, causal-K, direct to output)
    hgemm<0, 0, 1, 0><<<dim3(2, 16, 16), 256>>>(Ph, Pl, ve_h, ve_l, out, nullptr, nullptr,
                                                VDIM, SQ, SQ, VDIM, NH * VDIM,
                                                (long)SQ * SQ, (long)SQ * VDIM, (long)VDIM);
}

// round 16
// speedup vs baseline: 2.1688x; 1.0364x over previous
#include <cuda_runtime.h>
#include <cuda_bf16.h>
#include <math.h>

#define SQ 2048
#define NH 16
#define ID 128
#define ROPE 64
#define NOPE 128
#define VDIM 128
#define KVL 512
#define KC 192          /* compressed logit K-dim: NOPE + ROPE */
#define HIDD 2048
#define QLORA 1536
#define TOPKK 1024
#define EPSV 1e-6f
#define SCALV 0.08838834764831845f  /* 128^-0.5 */

typedef __nv_bfloat16 bf16;

// ---------------- scratch (device globals; no runtime allocation) ----------------
__device__ float g_ckv[SQ * ID];
__device__ float g_ik[SQ * ID];
__device__ float g_ql[SQ * NH * ID];
__device__ float g_iq[SQ * NH * ID];
__device__ float g_wt[SQ * NH];
__device__ float g_w[SQ * NH];
__device__ float g_score[SQ * SQ];
__device__ unsigned char g_mask[SQ * SQ];
__device__ float g_P[(size_t)NH * SQ * SQ];

// bf16 hi/lo split buffers (smooth-path GEMMs; 2-way split)
__device__ bf16 g_kp_h[SQ * KVL],    g_kp_l[SQ * KVL];
__device__ bf16 g_kvb_h[NH * (NOPE + VDIM) * KVL], g_kvb_l[NH * (NOPE + VDIM) * KVL];
__device__ bf16 g_qcat_h[(size_t)NH * SQ * KC], g_qcat_l[(size_t)NH * SQ * KC];
__device__ bf16 g_kcat_h[(size_t)NH * SQ * KC], g_kcat_l[(size_t)NH * SQ * KC];
__device__ bf16 g_ve_h[(size_t)NH * SQ * VDIM], g_ve_l[(size_t)NH * SQ * VDIM];
__device__ bf16 g_Ph[(size_t)NH * SQ * SQ], g_Pl[(size_t)NH * SQ * SQ];

// 3-way split buffers for the ql GEMM (selection path: needs fp32-level accuracy)
__device__ bf16 g_qlat3_h[SQ * QLORA], g_qlat3_m[SQ * QLORA], g_qlat3_l[SQ * QLORA];
__device__ bf16 g_wqb3_h[NH * ID * QLORA], g_wqb3_m[NH * ID * QLORA], g_wqb3_l[NH * ID * QLORA];

// ---------------- helpers ----------------
__device__ __forceinline__ unsigned smem_u32(const void* p) {
    return (unsigned)__cvta_generic_to_shared(p);
}
__device__ __forceinline__ void split1(float x, bf16& h, bf16& l) {
    h = __float2bfloat16(x);
    l = __float2bfloat16(x - __bfloat162float(h));
}
__device__ __forceinline__ void split3(float x, bf16& h, bf16& m, bf16& l) {
    h = __float2bfloat16(x);
    float r1 = x - __bfloat162float(h);
    m = __float2bfloat16(r1);
    l = __float2bfloat16(r1 - __bfloat162float(m));
}
__device__ __forceinline__ void ldsm_x4(unsigned& r0, unsigned& r1, unsigned& r2, unsigned& r3,
                                        unsigned addr) {
    asm volatile("ldmatrix.sync.aligned.m8n8.x4.shared.b16 {%0,%1,%2,%3},[%4];"
                 : "=r"(r0), "=r"(r1), "=r"(r2), "=r"(r3) : "r"(addr));
}
__device__ __forceinline__ void ldsm_x4_t(unsigned& r0, unsigned& r1, unsigned& r2, unsigned& r3,
                                          unsigned addr) {
    asm volatile("ldmatrix.sync.aligned.m8n8.x4.trans.shared.b16 {%0,%1,%2,%3},[%4];"
                 : "=r"(r0), "=r"(r1), "=r"(r2), "=r"(r3) : "r"(addr));
}
__device__ __forceinline__ void mma_bf16(float* c, const unsigned* a, const unsigned* b) {
    asm volatile(
        "mma.sync.aligned.m16n8k16.row.col.f32.bf16.bf16.f32 "
        "{%0,%1,%2,%3},{%4,%5,%6,%7},{%8,%9},{%0,%1,%2,%3};"
        : "+f"(c[0]), "+f"(c[1]), "+f"(c[2]), "+f"(c[3])
        : "r"(a[0]), "r"(a[1]), "r"(a[2]), "r"(a[3]), "r"(b[0]), "r"(b[1]));
}

// ---------------- bf16 hi/lo tensor GEMM (2-way, 3-term; smooth paths) ----------------
template <int TRANSB, int CAUSAL_N, int CAUSAL_K, int SPLIT_OUT>
__global__ __launch_bounds__(256) void hgemm(
        const bf16* __restrict__ Ahig, const bf16* __restrict__ Alog,
        const bf16* __restrict__ Bhig, const bf16* __restrict__ Blog,
        float* __restrict__ Cg, bf16* __restrict__ Chig, bf16* __restrict__ Clog,
        int N, int K, int lda, int ldb, int ldc, long aB, long bB, long cB) {
    constexpr int BM = 128, BN = 64, BK = 32;
    constexpr int BROWS = TRANSB ? 64 : 32;
    constexpr int BSTR = TRANSB ? 40 : 72;
    int bm = blockIdx.y, bn = blockIdx.x;
    if (CAUSAL_N && bn * BN > bm * BM + BM - 1) return;
    long z = blockIdx.z;
    const bf16* Ahi = Ahig + z * aB;
    const bf16* Alo = Alog + z * aB;
    const bf16* Bhi = Bhig + z * bB;
    const bf16* Blo = Blog + z * bB;

    __shared__ __align__(16) bf16 As[2][BM * 40];
    __shared__ __align__(16) bf16 Bs[2][BROWS * BSTR];

    int tid = threadIdx.x, lane = tid & 31, warp = tid >> 5;
    int wm = warp >> 1, wn = warp & 1;

    float acc[2][4][4];
#pragma unroll
    for (int i = 0; i < 2; i++)
#pragma unroll
        for (int j = 0; j < 4; j++)
#pragma unroll
            for (int k = 0; k < 4; k++) acc[i][j][k] = 0.f;

    int kEnd = CAUSAL_K ? (bm * BM + BM < K ? bm * BM + BM : K) : K;

    const int arow = tid >> 1, acol = (tid & 1) * 16;
    const bf16* aph = Ahi + (long)(bm * BM + arow) * lda + acol;
    const bf16* apl = Alo + (long)(bm * BM + arow) * lda + acol;
    const bf16 *bph, *bpl;
    int brow, bcol;
    if (TRANSB) {
        brow = tid >> 2; bcol = (tid & 3) * 8;
        bph = Bhi + (long)(bn * BN + brow) * ldb + bcol;
        bpl = Blo + (long)(bn * BN + brow) * ldb + bcol;
    } else {
        brow = tid >> 3; bcol = (tid & 7) * 8;
        bph = Bhi + (long)brow * ldb + bn * BN + bcol;
        bpl = Blo + (long)brow * ldb + bn * BN + bcol;
    }

    for (int k0 = 0; k0 < kEnd; k0 += BK) {
        uint4 vah0 = *(const uint4*)(aph + k0);
        uint4 vah1 = *(const uint4*)(aph + k0 + 8);
        uint4 val0 = *(const uint4*)(apl + k0);
        uint4 val1 = *(const uint4*)(apl + k0 + 8);
        uint4 vbh, vbl;
        if (TRANSB) {
            vbh = *(const uint4*)(bph + k0);
            vbl = *(const uint4*)(bpl + k0);
        } else {
            vbh = *(const uint4*)(bph + (long)k0 * ldb);
            vbl = *(const uint4*)(bpl + (long)k0 * ldb);
        }
        __syncthreads();
        *(uint4*)&As[0][arow * 40 + acol] = vah0;
        *(uint4*)&As[0][arow * 40 + acol + 8] = vah1;
        *(uint4*)&As[1][arow * 40 + acol] = val0;
        *(uint4*)&As[1][arow * 40 + acol + 8] = val1;
        *(uint4*)&Bs[0][brow * BSTR + bcol] = vbh;
        *(uint4*)&Bs[1][brow * BSTR + bcol] = vbl;
        __syncthreads();

#pragma unroll
        for (int kk = 0; kk < BK; kk += 16) {
            unsigned ah[2][4], al[2][4];
#pragma unroll
            for (int mb = 0; mb < 2; mb++) {
                int r = wm * 32 + mb * 16 + (lane & 15);
                int c = kk + (lane >> 4) * 8;
                ldsm_x4(ah[mb][0], ah[mb][1], ah[mb][2], ah[mb][3],
                        smem_u32(&As[0][r * 40 + c]));
                ldsm_x4(al[mb][0], al[mb][1], al[mb][2], al[mb][3],
                        smem_u32(&As[1][r * 40 + c]));
            }
            unsigned bh[4][2], bl[4][2];
#pragma unroll
            for (int nb2 = 0; nb2 < 2; nb2++) {
                if (TRANSB) {
                    int n = wn * 32 + nb2 * 16 + (lane & 7) + ((lane >> 4) & 1) * 8;
                    int k = kk + ((lane >> 3) & 1) * 8;
                    ldsm_x4(bh[nb2 * 2][0], bh[nb2 * 2][1], bh[nb2 * 2 + 1][0], bh[nb2 * 2 + 1][1],
                            smem_u32(&Bs[0][n * BSTR + k]));
                    ldsm_x4(bl[nb2 * 2][0], bl[nb2 * 2][1], bl[nb2 * 2 + 1][0], bl[nb2 * 2 + 1][1],
                            smem_u32(&Bs[1][n * BSTR + k]));
                } else {
                    int k = kk + (lane & 7) + ((lane >> 3) & 1) * 8;
                    int n = wn * 32 + nb2 * 16 + ((lane >> 4) & 1) * 8;
                    ldsm_x4_t(bh[nb2 * 2][0], bh[nb2 * 2][1], bh[nb2 * 2 + 1][0], bh[nb2 * 2 + 1][1],
                              smem_u32(&Bs[0][k * BSTR + n]));
                    ldsm_x4_t(bl[nb2 * 2][0], bl[nb2 * 2][1], bl[nb2 * 2 + 1][0], bl[nb2 * 2 + 1][1],
                              smem_u32(&Bs[1][k * BSTR + n]));
                }
            }
#pragma unroll
            for (int mb = 0; mb < 2; mb++)
#pragma unroll
                for (int nb = 0; nb < 4; nb++) {
                    mma_bf16(acc[mb][nb], ah[mb], bh[nb]);  // hi*hi
                    mma_bf16(acc[mb][nb], ah[mb], bl[nb]);  // hi*lo
                    mma_bf16(acc[mb][nb], al[mb], bh[nb]);  // lo*hi
                }
        }
    }

#pragma unroll
    for (int mb = 0; mb < 2; mb++) {
        int r = bm * BM + wm * 32 + mb * 16 + (lane >> 2);
#pragma unroll
        for (int nb = 0; nb < 4; nb++) {
            int c = bn * BN + wn * 32 + nb * 8 + (lane & 3) * 2;
            if (SPLIT_OUT) {
                bf16 h0, l0, h1, l1;
                split1(acc[mb][nb][0], h0, l0);
                split1(acc[mb][nb][1], h1, l1);
                *(__nv_bfloat162*)&Chig[z * cB + (long)r * ldc + c] = __nv_bfloat162(h0, h1);
                *(__nv_bfloat162*)&Clog[z * cB + (long)r * ldc + c] = __nv_bfloat162(l0, l1);
                split1(acc[mb][nb][2], h0, l0);
                split1(acc[mb][nb][3], h1, l1);
                *(__nv_bfloat162*)&Chig[z * cB + (long)(r + 8) * ldc + c] = __nv_bfloat162(h0, h1);
                *(__nv_bfloat162*)&Clog[z * cB + (long)(r + 8) * ldc + c] = __nv_bfloat162(l0, l1);
            } else {
                *(float2*)&Cg[z * cB + (long)r * ldc + c] =
                    make_float2(acc[mb][nb][0], acc[mb][nb][1]);
                *(float2*)&Cg[z * cB + (long)(r + 8) * ldc + c] =
                    make_float2(acc[mb][nb][2], acc[mb][nb][3]);
            }
        }
    }
}

// ---------------- 3-way bf16 split tensor GEMM (fp32-accurate; ql) ----------------
// C = A @ B^T with A = Ah+Am+Al, B = Bh+Bm+Bl; 6 product terms (hh,hm,mh,mm,hl,lh);
// omitted terms are O(2^-27) — below fp32 rounding. TRANSB only. fp32 output.
__global__ __launch_bounds__(256) void hgemm3(
        const bf16* __restrict__ Ah, const bf16* __restrict__ Am, const bf16* __restrict__ Al,
        const bf16* __restrict__ Bh, const bf16* __restrict__ Bm, const bf16* __restrict__ Bl,
        float* __restrict__ Cg, int N, int K, int lda, int ldb, int ldc) {
    constexpr int BM = 128, BN = 64, BK = 32;
    constexpr int BSTR = 40;
    int bm = blockIdx.y, bn = blockIdx.x;

    __shared__ __align__(16) bf16 As[3][BM * 40];
    __shared__ __align__(16) bf16 Bs[3][BN * BSTR];

    int tid = threadIdx.x, lane = tid & 31, warp = tid >> 5;
    int wm = warp >> 1, wn = warp & 1;

    float acc[2][4][4];
#pragma unroll
    for (int i = 0; i < 2; i++)
#pragma unroll
        for (int j = 0; j < 4; j++)
#pragma unroll
            for (int k = 0; k < 4; k++) acc[i][j][k] = 0.f;

    const int arow = tid >> 1, acol = (tid & 1) * 16;
    const bf16* ap0 = Ah + (long)(bm * BM + arow) * lda + acol;
    const bf16* ap1 = Am + (long)(bm * BM + arow) * lda + acol;
    const bf16* ap2 = Al + (long)(bm * BM + arow) * lda + acol;
    const int brow = tid >> 2, bcol = (tid & 3) * 8;
    const bf16* bp0 = Bh + (long)(bn * BN + brow) * ldb + bcol;
    const bf16* bp1 = Bm + (long)(bn * BN + brow) * ldb + bcol;
    const bf16* bp2 = Bl + (long)(bn * BN + brow) * ldb + bcol;

    for (int k0 = 0; k0 < K; k0 += BK) {
        uint4 va00 = *(const uint4*)(ap0 + k0);
        uint4 va01 = *(const uint4*)(ap0 + k0 + 8);
        uint4 va10 = *(const uint4*)(ap1 + k0);
        uint4 va11 = *(const uint4*)(ap1 + k0 + 8);
        uint4 va20 = *(const uint4*)(ap2 + k0);
        uint4 va21 = *(const uint4*)(ap2 + k0 + 8);
        uint4 vb0 = *(const uint4*)(bp0 + k0);
        uint4 vb1 = *(const uint4*)(bp1 + k0);
        uint4 vb2 = *(const uint4*)(bp2 + k0);
        __syncthreads();
        *(uint4*)&As[0][arow * 40 + acol] = va00;
        *(uint4*)&As[0][arow * 40 + acol + 8] = va01;
        *(uint4*)&As[1][arow * 40 + acol] = va10;
        *(uint4*)&As[1][arow * 40 + acol + 8] = va11;
        *(uint4*)&As[2][arow * 40 + acol] = va20;
        *(uint4*)&As[2][arow * 40 + acol + 8] = va21;
        *(uint4*)&Bs[0][brow * BSTR + bcol] = vb0;
        *(uint4*)&Bs[1][brow * BSTR + bcol] = vb1;
        *(uint4*)&Bs[2][brow * BSTR + bcol] = vb2;
        __syncthreads();

#pragma unroll
        for (int kk = 0; kk < BK; kk += 16) {
            unsigned ah[2][4], am[2][4], al[2][4];
#pragma unroll
            for (int mb = 0; mb < 2; mb++) {
                int r = wm * 32 + mb * 16 + (lane & 15);
                int c = kk + (lane >> 4) * 8;
                ldsm_x4(ah[mb][0], ah[mb][1], ah[mb][2], ah[mb][3], smem_u32(&As[0][r * 40 + c]));
                ldsm_x4(am[mb][0], am[mb][1], am[mb][2], am[mb][3], smem_u32(&As[1][r * 40 + c]));
                ldsm_x4(al[mb][0], al[mb][1], al[mb][2], al[mb][3], smem_u32(&As[2][r * 40 + c]));
            }
            unsigned bh[4][2], bm_[4][2], bl[4][2];
#pragma unroll
            for (int nb2 = 0; nb2 < 2; nb2++) {
                int n = wn * 32 + nb2 * 16 + (lane & 7) + ((lane >> 4) & 1) * 8;
                int k = kk + ((lane >> 3) & 1) * 8;
                ldsm_x4(bh[nb2 * 2][0], bh[nb2 * 2][1], bh[nb2 * 2 + 1][0], bh[nb2 * 2 + 1][1],
                        smem_u32(&Bs[0][n * BSTR + k]));
                ldsm_x4(bm_[nb2 * 2][0], bm_[nb2 * 2][1], bm_[nb2 * 2 + 1][0], bm_[nb2 * 2 + 1][1],
                        smem_u32(&Bs[1][n * BSTR + k]));
                ldsm_x4(bl[nb2 * 2][0], bl[nb2 * 2][1], bl[nb2 * 2 + 1][0], bl[nb2 * 2 + 1][1],
                        smem_u32(&Bs[2][n * BSTR + k]));
            }
#pragma unroll
            for (int mb = 0; mb < 2; mb++)
#pragma unroll
                for (int nb = 0; nb < 4; nb++) {
                    mma_bf16(acc[mb][nb], ah[mb], bh[nb]);   // h*h
                    mma_bf16(acc[mb][nb], ah[mb], bm_[nb]);  // h*m
                    mma_bf16(acc[mb][nb], am[mb], bh[nb]);   // m*h
                    mma_bf16(acc[mb][nb], am[mb], bm_[nb]);  // m*m
                    mma_bf16(acc[mb][nb], ah[mb], bl[nb]);   // h*l
                    mma_bf16(acc[mb][nb], al[mb], bh[nb]);   // l*h
                }
        }
    }

#pragma unroll
    for (int mb = 0; mb < 2; mb++) {
        int r = bm * BM + wm * 32 + mb * 16 + (lane >> 2);
#pragma unroll
        for (int nb = 0; nb < 4; nb++) {
            int c = bn * BN + wn * 32 + nb * 8 + (lane & 3) * 2;
            *(float2*)&Cg[(long)r * ldc + c] = make_float2(acc[mb][nb][0], acc[mb][nb][1]);
            *(float2*)&Cg[(long)(r + 8) * ldc + c] = make_float2(acc[mb][nb][2], acc[mb][nb][3]);
        }
    }
}

// ---------------- fp32 SGEMM (selection path: exact; ckv + wproj) ----------------
template <int TRANSB, int CAUSAL_N, int CAUSAL_K>
__global__ __launch_bounds__(256) void sgemm2(
        const float* __restrict__ Ag, const float* __restrict__ Bg,
        float* __restrict__ Cg, int M, int N, int K,
        int lda, int ldb, int ldc, long aB, long bB, long cB) {
    constexpr int BM = 128, BN = 64, BK = 16;
    int bm = blockIdx.y, bn = blockIdx.x;
    if (CAUSAL_N && bn * BN > bm * BM + BM - 1) return;
    const float* A = Ag + (long)blockIdx.z * aB;
    const float* B = Bg + (long)blockIdx.z * bB;
    float* C = Cg + (long)blockIdx.z * cB;
    __shared__ float As[2][BK][BM];
    __shared__ float Bs[2][BK][BN];
    const int tid = threadIdx.x;
    const int tx = tid & 15, ty = tid >> 4;
    const int ar = tid >> 1, ac = (tid & 1) * 8;
    const int br = TRANSB ? (tid >> 2) : (tid >> 4);
    const int bc = TRANSB ? ((tid & 3) * 4) : ((tid & 15) * 4);
    float acc[8][4];
#pragma unroll
    for (int i = 0; i < 8; i++)
#pragma unroll
        for (int j = 0; j < 4; j++) acc[i][j] = 0.f;
    int kEnd = CAUSAL_K ? min(K, bm * BM + BM) : K;
    int nT = kEnd >> 4;
    const float* aPtr = A + (long)(bm * BM + ar) * lda + ac;
    {
        float4 a0 = *(const float4*)(aPtr);
        float4 a1 = *(const float4*)(aPtr + 4);
        As[0][ac + 0][ar] = a0.x; As[0][ac + 1][ar] = a0.y;
        As[0][ac + 2][ar] = a0.z; As[0][ac + 3][ar] = a0.w;
        As[0][ac + 4][ar] = a1.x; As[0][ac + 5][ar] = a1.y;
        As[0][ac + 6][ar] = a1.z; As[0][ac + 7][ar] = a1.w;
        float4 bv = make_float4(0.f, 0.f, 0.f, 0.f);
        if (TRANSB) {
            int brow = bn * BN + br;
            if (brow < N) bv = *(const float4*)(B + (long)brow * ldb + bc);
            Bs[0][bc + 0][br] = bv.x; Bs[0][bc + 1][br] = bv.y;
            Bs[0][bc + 2][br] = bv.z; Bs[0][bc + 3][br] = bv.w;
        } else {
            int bcol = bn * BN + bc;
            if (bcol < N) bv = *(const float4*)(B + (long)br * ldb + bcol);
            *(float4*)&Bs[0][br][bc] = bv;
        }
    }
    __syncthreads();
    for (int t = 0; t < nT; t++) {
        int cur = t & 1;
        float4 pa0, pa1, pbv;
        bool has = (t + 1 < nT);
        if (has) {
            int k0 = (t + 1) << 4;
            pa0 = *(const float4*)(aPtr + k0);
            pa1 = *(const float4*)(aPtr + k0 + 4);
            pbv = make_float4(0.f, 0.f, 0.f, 0.f);
            if (TRANSB) {
                int brow = bn * BN + br;
                if (brow < N) pbv = *(const float4*)(B + (long)brow * ldb + k0 + bc);
            } else {
                int bcol = bn * BN + bc;
                if (bcol < N) pbv = *(const float4*)(B + (long)(k0 + br) * ldb + bcol);
            }
        }
#pragma unroll
        for (int kk = 0; kk < BK; kk++) {
            float4 a0 = *(const float4*)&As[cur][kk][ty * 8];
            float4 a1 = *(const float4*)&As[cur][kk][ty * 8 + 4];
            float4 b4 = *(const float4*)&Bs[cur][kk][tx * 4];
            float av[8] = {a0.x, a0.y, a0.z, a0.w, a1.x, a1.y, a1.z, a1.w};
            float bv2[4] = {b4.x, b4.y, b4.z, b4.w};
#pragma unroll
            for (int i = 0; i < 8; i++)
#pragma unroll
                for (int j = 0; j < 4; j++) acc[i][j] += av[i] * bv2[j];
        }
        if (has) {
            int nxt = cur ^ 1;
            As[nxt][ac + 0][ar] = pa0.x; As[nxt][ac + 1][ar] = pa0.y;
            As[nxt][ac + 2][ar] = pa0.z; As[nxt][ac + 3][ar] = pa0.w;
            As[nxt][ac + 4][ar] = pa1.x; As[nxt][ac + 5][ar] = pa1.y;
            As[nxt][ac + 6][ar] = pa1.z; As[nxt][ac + 7][ar] = pa1.w;
            if (TRANSB) {
                Bs[nxt][bc + 0][br] = pbv.x; Bs[nxt][bc + 1][br] = pbv.y;
                Bs[nxt][bc + 2][br] = pbv.z; Bs[nxt][bc + 3][br] = pbv.w;
            } else {
                *(float4*)&Bs[nxt][br][bc] = pbv;
            }
            __syncthreads();
        }
    }
#pragma unroll
    for (int i = 0; i < 8; i++) {
        int row = bm * BM + ty * 8 + i;
        float* cp = C + (long)row * ldc + bn * BN + tx * 4;
#pragma unroll
        for (int j = 0; j < 4; j++) {
            if (bn * BN + tx * 4 + j < N) cp[j] = acc[i][j];
        }
    }
}

// ---------------- split kernels ----------------
__global__ void split_kernel(const float* __restrict__ x, bf16* __restrict__ h,
                             bf16* __restrict__ l, long n) {
    long i = ((long)blockIdx.x * 256 + threadIdx.x) * 4;
    if (i >= n) return;
    float4 v = *(const float4*)(x + i);
    bf16 h0, l0, h1, l1;
    split1(v.x, h0, l0); split1(v.y, h1, l1);
    *(__nv_bfloat162*)&h[i] = __nv_bfloat162(h0, h1);
    *(__nv_bfloat162*)&l[i] = __nv_bfloat162(l0, l1);
    split1(v.z, h0, l0); split1(v.w, h1, l1);
    *(__nv_bfloat162*)&h[i + 2] = __nv_bfloat162(h0, h1);
    *(__nv_bfloat162*)&l[i + 2] = __nv_bfloat162(l0, l1);
}

__global__ void split3_kernel(const float* __restrict__ x, bf16* __restrict__ h,
                              bf16* __restrict__ m, bf16* __restrict__ l, long n) {
    long i = ((long)blockIdx.x * 256 + threadIdx.x) * 4;
    if (i >= n) return;
    float4 v = *(const float4*)(x + i);
    bf16 h0, m0, l0, h1, m1, l1;
    split3(v.x, h0, m0, l0); split3(v.y, h1, m1, l1);
    *(__nv_bfloat162*)&h[i] = __nv_bfloat162(h0, h1);
    *(__nv_bfloat162*)&m[i] = __nv_bfloat162(m0, m1);
    *(__nv_bfloat162*)&l[i] = __nv_bfloat162(l0, l1);
    split3(v.z, h0, m0, l0); split3(v.w, h1, m1, l1);
    *(__nv_bfloat162*)&h[i + 2] = __nv_bfloat162(h0, h1);
    *(__nv_bfloat162*)&m[i + 2] = __nv_bfloat162(m0, m1);
    *(__nv_bfloat162*)&l[i + 2] = __nv_bfloat162(l0, l1);
}

// ---------------- index_k: rope(interleaved) + rmsnorm ----------------
__global__ void indexk_kernel(const float* __restrict__ ckv, const float* __restrict__ cosb,
                              const float* __restrict__ sinb, const float* __restrict__ knorm,
                              float* __restrict__ ik) {
    int s = blockIdx.x, j = threadIdx.x;  // 128 threads
    __shared__ float sh[128];
    __shared__ float red[128];
    sh[j] = ckv[s * 128 + j];
    __syncthreads();
    float x = (j >= 64) ? sh[j] * sh[j] : 0.f;
    red[j] = x;
    __syncthreads();
    for (int t = 64; t > 0; t >>= 1) {
        if (j < t) red[j] += red[j + t];
        __syncthreads();
    }
    float rstd = rsqrtf(red[0] / 64.f + EPSV);
    float o;
    if (j < 64) {
        float c = cosb[s * 64 + j], si = sinb[s * 64 + j];
        int jj = j & 31;
        float e = sh[2 * jj], od = sh[2 * jj + 1];
        o = (j < 32) ? (e * c - od * si) : (od * c + e * si);
    } else {
        o = sh[j] * rstd * knorm[j - 64];
    }
    ik[s * 128 + j] = o;
}

// ---------------- index_q: rope first 64 of each 128-chunk ----------------
__global__ void indexq_kernel(const float* __restrict__ ql, const float* __restrict__ cosb,
                              const float* __restrict__ sinb, float* __restrict__ iq) {
    int s = blockIdx.x;
    int tid = threadIdx.x;  // 256
    __shared__ float sh[2048];
    for (int i = tid; i < 2048; i += 256) sh[i] = ql[(long)s * 2048 + i];
    __syncthreads();
    for (int i = tid; i < 2048; i += 256) {
        int h = i >> 7, j = i & 127;
        float o;
        if (j < 64) {
            int jj = j & 31;
            float c = cosb[s * 64 + j], si = sinb[s * 64 + j];
            float e = sh[h * 128 + 2 * jj], od = sh[h * 128 + 2 * jj + 1];
            o = (j < 32) ? (e * c - od * si) : (od * c + e * si);
        } else {
            o = sh[h * 128 + j];
        }
        iq[(long)s * 2048 + i] = o;
    }
}

__global__ void absbias_kernel(const float* __restrict__ wt, const float* __restrict__ b,
                               float* __restrict__ w) {
    int i = blockIdx.x * 256 + threadIdx.x;
    if (i < SQ * NH) w[i] = fabsf(wt[i] + b[i & 15]);
}

// qcat[h][s][0:128]=q_pass, [128:192]=q_rot, split to hi/lo
__global__ void qcat_split(const float* __restrict__ qp, const float* __restrict__ qr,
                           bf16* __restrict__ qh, bf16* __restrict__ qlo) {
    long i = (long)blockIdx.x * 256 + threadIdx.x;
    if (i >= (long)NH * SQ * KC) return;
    int d = (int)(i % KC);
    long r = i / KC;
    int s = (int)(r % SQ);
    int h = (int)(r / SQ);
    float v = (d < NOPE) ? qp[((long)h * SQ + s) * NOPE + d]
                         : qr[((long)h * SQ + s) * ROPE + (d - NOPE)];
    split1(v, qh[i], qlo[i]);
}

// kcat[h][k][128:192] = k_rot[k] split (cols 0:128 from k_eff GEMM epilogue)
__global__ void krot_split(const float* __restrict__ kr, bf16* __restrict__ kh,
                           bf16* __restrict__ kl) {
    long i = (long)blockIdx.x * 256 + threadIdx.x;
    if (i >= (long)NH * SQ * ROPE) return;
    int j = (int)(i % ROPE);
    long r = i / ROPE;
    int s = (int)(r % SQ);
    int h = (int)(r / SQ);
    long o = ((long)h * SQ + s) * KC + NOPE + j;
    split1(kr[s * ROPE + j], kh[o], kl[o]);
}

// ---------------- indexer score: 32x32 tile, 64 thr, 4x4 micro (fp32, exact) --------
__global__ __launch_bounds__(64) void idx_score2(const float* __restrict__ iq,
                                                 const float* __restrict__ ik,
                                                 const float* __restrict__ w,
                                                 float* __restrict__ score) {
    int bq = blockIdx.y, bk = blockIdx.x;
    if (bk > bq) return;
    __shared__ float iqs[32][132];
    __shared__ float iks[32][132];
    __shared__ float ws[16][32];
    int t = threadIdx.x;
#pragma unroll
    for (int c = 0; c < 16; c++) {
        int chunk = t + 64 * c;
        int c4 = chunk & 31, r = chunk >> 5;
        float4 v = *(const float4*)&ik[(bk * 32 + r) * 128 + c4 * 4];
        *(float4*)&iks[r][c4 * 4] = v;
    }
    for (int i = t; i < 512; i += 64) {
        int r = i >> 4, h = i & 15;
        ws[h][r] = w[(bq * 32 + r) * 16 + h];
    }
    int tq = t >> 3, tk = t & 7;
    float sacc[4][4];
#pragma unroll
    for (int i = 0; i < 4; i++)
#pragma unroll
        for (int j = 0; j < 4; j++) sacc[i][j] = 0.f;
    for (int h = 0; h < 16; h++) {
        __syncthreads();
#pragma unroll
        for (int c = 0; c < 16; c++) {
            int chunk = t + 64 * c;
            int c4 = chunk & 31, r = chunk >> 5;
            float4 v = *(const float4*)&iq[((long)(bq * 32 + r) * 16 + h) * 128 + c4 * 4];
            *(float4*)&iqs[r][c4 * 4] = v;
        }
        __syncthreads();
        float d[4][4];
#pragma unroll
        for (int i = 0; i < 4; i++)
#pragma unroll
            for (int j = 0; j < 4; j++) d[i][j] = 0.f;
#pragma unroll 4
        for (int c4 = 0; c4 < 32; c4++) {
            float4 A4[4], B4[4];
#pragma unroll
            for (int i = 0; i < 4; i++) A4[i] = *(const float4*)&iqs[tq * 4 + i][c4 * 4];
#pragma unroll
            for (int j = 0; j < 4; j++) B4[j] = *(const float4*)&iks[tk * 4 + j][c4 * 4];
#pragma unroll
            for (int i = 0; i < 4; i++)
#pragma unroll
                for (int j = 0; j < 4; j++)
                    d[i][j] += A4[i].x * B4[j].x + A4[i].y * B4[j].y +
                               A4[i].z * B4[j].z + A4[i].w * B4[j].w;
        }
#pragma unroll
        for (int i = 0; i < 4; i++) {
            float wv = ws[h][tq * 4 + i];
#pragma unroll
            for (int j = 0; j < 4; j++) sacc[i][j] += wv * fmaxf(d[i][j], 0.f);
        }
    }
#pragma unroll
    for (int i = 0; i < 4; i++) {
        long row = (long)(bq * 32 + tq * 4 + i);
        float4 o = make_float4(sacc[i][0] * SCALV, sacc[i][1] * SCALV,
                               sacc[i][2] * SCALV, sacc[i][3] * SCALV);
        *(float4*)&score[row * SQ + bk * 32 + tk * 4] = o;
    }
}

// ---------------- per-query top-1024 via radix select ----------------
__global__ void topk_kernel(const float* __restrict__ score, unsigned char* __restrict__ mask) {
    int q = blockIdx.x;
    int n = q + 1;
    int tid = threadIdx.x;  // 256
    unsigned char* mrow = mask + (long)q * SQ;
    if (q < TOPKK) {
        for (int k = tid; k < SQ; k += 256) mrow[k] = (k <= q) ? 1 : 0;
        return;
    }
    const float* srow = score + (long)q * SQ;
    __shared__ unsigned int sbits[SQ];
    __shared__ int hist[256];
    __shared__ unsigned int sh_prefix;
    __shared__ int sh_kk;
    for (int k = tid; k < n; k += 256) sbits[k] = __float_as_uint(srow[k]);
    if (tid == 0) { sh_prefix = 0u; sh_kk = TOPKK; }
    __syncthreads();
    for (int pass = 0; pass < 4; pass++) {
        int shift = 24 - 8 * pass;
        if (tid < 256) hist[tid] = 0;
        __syncthreads();
        unsigned int pfx = sh_prefix;
        for (int k = tid; k < n; k += 256) {
            unsigned int v = sbits[k];
            if ((unsigned int)(((unsigned long long)v) >> (shift + 8)) == pfx)
                atomicAdd(&hist[(v >> shift) & 255], 1);
        }
        __syncthreads();
        if (tid == 0) {
            int kk = sh_kk;
            int d = 255;
            for (; d >= 0; d--) {
                if (kk <= hist[d]) break;
                kk -= hist[d];
            }
            sh_prefix = (pfx << 8) | (unsigned int)d;
            sh_kk = kk;
        }
        __syncthreads();
    }
    unsigned int T = sh_prefix;
    int kk = sh_kk;
    for (int k = tid; k < SQ; k += 256) {
        unsigned char m = 0;
        if (k < n) {
            unsigned int v = sbits[k];
            if (v > T) m = 1;
            else if (v == T) {
                int rank = 0;
                for (int j = 0; j < k; j++) rank += (sbits[j] == T) ? 1 : 0;
                m = (rank < kk) ? 1 : 0;
            }
        }
        mrow[k] = m;
    }
}

// ---------------- masked softmax: reads fp32 logits, writes hi/lo bf16 probs --------
__global__ void softmax_split(const float* __restrict__ P, const unsigned char* __restrict__ mask,
                              bf16* __restrict__ Ph, bf16* __restrict__ Pl) {
    int q = blockIdx.x, h = blockIdx.y;
    int n = (q & ~127) + 128;  // kLim (AV only reads k < kLim)
    const float* row = P + ((long)h * SQ + q) * SQ;
    bf16* rh = Ph + ((long)h * SQ + q) * SQ;
    bf16* rl = Pl + ((long)h * SQ + q) * SQ;
    const unsigned char* mrow = mask + (long)q * SQ;
    int tid = threadIdx.x;  // 256
    float v[8];
    float mx = -1e30f;
#pragma unroll
    for (int i = 0; i < 8; i++) {
        int k = i * 256 + tid;
        float val = -1e30f;
        if (k < n && mrow[k]) val = row[k] * SCALV;
        v[i] = val;
        mx = fmaxf(mx, val);
    }
    __shared__ float red[256];
    red[tid] = mx;
    __syncthreads();
    for (int s = 128; s > 0; s >>= 1) {
        if (tid < s) red[tid] = fmaxf(red[tid], red[tid + s]);
        __syncthreads();
    }
    mx = red[0];
    __syncthreads();
    float sum = 0.f;
#pragma unroll
    for (int i = 0; i < 8; i++) {
        float e = (v[i] > -1e29f) ? __expf(v[i] - mx) : 0.f;
        v[i] = e;
        sum += e;
    }
    red[tid] = sum;
    __syncthreads();
    for (int s = 128; s > 0; s >>= 1) {
        if (tid < s) red[tid] += red[tid + s];
        __syncthreads();
    }
    float inv = 1.f / red[0];
#pragma unroll
    for (int i = 0; i < 8; i++) {
        int k = i * 256 + tid;
        if (k < n) {
            bf16 hh, ll;
            split1(v[i] * inv, hh, ll);
            rh[k] = hh;
            rl[k] = ll;
        }
    }
}

// ---------------- launch ----------------
extern "C" void kernel_launch(void* const* d_in, const int* in_sizes, int n_in,
                              void* d_out, int out_size) {
    const float* q_latent = (const float*)d_in[0];
    const float* hidden   = (const float*)d_in[1];
    const float* cosb     = (const float*)d_in[2];
    const float* sinb     = (const float*)d_in[3];
    const float* q_pass   = (const float*)d_in[4];
    const float* q_rot    = (const float*)d_in[5];
    const float* k_pass   = (const float*)d_in[6];
    const float* k_rot    = (const float*)d_in[7];
    /* d_in[8] = position_ids (unused) */
    const float* kv_b     = (const float*)d_in[9];
    const float* wq_b     = (const float*)d_in[10];
    const float* wk       = (const float*)d_in[11];
    const float* knorm    = (const float*)d_in[12];
    const float* wproj    = (const float*)d_in[13];
    const float* wproj_b  = (const float*)d_in[14];
    float* out = (float*)d_out;

    float *ckv, *ik, *ql, *iq, *wt, *w, *score, *P;
    unsigned char* mask;
    bf16 *kp_h, *kp_l, *kvb_h, *kvb_l, *qcat_h, *qcat_l, *kcat_h, *kcat_l;
    bf16 *ve_h, *ve_l, *Ph, *Pl;
    bf16 *ql3h, *ql3m, *ql3l, *wq3h, *wq3m, *wq3l;
    cudaGetSymbolAddress((void**)&ckv, g_ckv);
    cudaGetSymbolAddress((void**)&ik, g_ik);
    cudaGetSymbolAddress((void**)&ql, g_ql);
    cudaGetSymbolAddress((void**)&iq, g_iq);
    cudaGetSymbolAddress((void**)&wt, g_wt);
    cudaGetSymbolAddress((void**)&w, g_w);
    cudaGetSymbolAddress((void**)&score, g_score);
    cudaGetSymbolAddress((void**)&mask, g_mask);
    cudaGetSymbolAddress((void**)&P, g_P);
    cudaGetSymbolAddress((void**)&kp_h, g_kp_h);     cudaGetSymbolAddress((void**)&kp_l, g_kp_l);
    cudaGetSymbolAddress((void**)&kvb_h, g_kvb_h);   cudaGetSymbolAddress((void**)&kvb_l, g_kvb_l);
    cudaGetSymbolAddress((void**)&qcat_h, g_qcat_h); cudaGetSymbolAddress((void**)&qcat_l, g_qcat_l);
    cudaGetSymbolAddress((void**)&kcat_h, g_kcat_h); cudaGetSymbolAddress((void**)&kcat_l, g_kcat_l);
    cudaGetSymbolAddress((void**)&ve_h, g_ve_h);     cudaGetSymbolAddress((void**)&ve_l, g_ve_l);
    cudaGetSymbolAddress((void**)&Ph, g_Ph);         cudaGetSymbolAddress((void**)&Pl, g_Pl);
    cudaGetSymbolAddress((void**)&ql3h, g_qlat3_h);  cudaGetSymbolAddress((void**)&ql3m, g_qlat3_m);
    cudaGetSymbolAddress((void**)&ql3l, g_qlat3_l);
    cudaGetSymbolAddress((void**)&wq3h, g_wqb3_h);   cudaGetSymbolAddress((void**)&wq3m, g_wqb3_m);
    cudaGetSymbolAddress((void**)&wq3l, g_wqb3_l);

    // 0. splits
    {
        long n;
        n = (long)SQ * KVL;        split_kernel<<<(int)(n / 4 / 256), 256>>>(k_pass, kp_h, kp_l, n);
        n = (long)NH * (NOPE + VDIM) * KVL;
                                   split_kernel<<<(int)(n / 4 / 256), 256>>>(kv_b, kvb_h, kvb_l, n);
        n = (long)SQ * QLORA;      split3_kernel<<<(int)(n / 4 / 256), 256>>>(q_latent, ql3h, ql3m, ql3l, n);
        n = (long)NH * ID * QLORA; split3_kernel<<<(int)(n / 4 / 256), 256>>>(wq_b, wq3h, wq3m, wq3l, n);
    }
    // 1. ckv = hidden @ wk^T   (fp32 EXACT — feeds index_k -> top-k selection)
    sgemm2<1, 0, 0><<<dim3(2, 16, 1), 256>>>(hidden, wk, ckv, SQ, ID, HIDD,
                                             HIDD, HIDD, ID, 0, 0, 0);
    // 2. index_k
    indexk_kernel<<<SQ, 128>>>(ckv, cosb, sinb, knorm, ik);
    // 3. ql = q_latent @ wq_b^T   (3-way bf16 split tensor GEMM, fp32-accurate)
    hgemm3<<<dim3(32, 16, 1), 256>>>(ql3h, ql3m, ql3l, wq3h, wq3m, wq3l, ql,
                                     NH * ID, QLORA, QLORA, QLORA, NH * ID);
    // 4. index_q
    indexq_kernel<<<SQ, 256>>>(ql, cosb, sinb, iq);
    // 5. w = |hidden @ wproj^T + b|   (tiny fp32 GEMM)
    sgemm2<1, 0, 0><<<dim3(1, 16, 1), 256>>>(hidden, wproj, wt, SQ, NH, HIDD,
                                             HIDD, HIDD, NH, 0, 0, 0);
    absbias_kernel<<<(SQ * NH + 255) / 256, 256>>>(wt, wproj_b, w);
    // 6. k_eff[h] = k_pass @ k_b[h]^T -> kcat hi/lo cols 0:128  (tensor, SPLIT_OUT)
    hgemm<1, 0, 0, 1><<<dim3(2, 16, 16), 256>>>(kp_h, kp_l, kvb_h, kvb_l, nullptr, kcat_h, kcat_l,
                                                NOPE, KVL, KVL, KVL, KC,
                                                0L, (long)(NOPE + VDIM) * KVL, (long)SQ * KC);
    // 7. kcat cols 128:192 = k_rot (split)
    krot_split<<<(int)(((long)NH * SQ * ROPE + 255) / 256), 256>>>(k_rot, kcat_h, kcat_l);
    // 8. v_eff[h] = k_pass @ v_b[h]^T   (tensor, SPLIT_OUT)
    hgemm<1, 0, 0, 1><<<dim3(2, 16, 16), 256>>>(kp_h, kp_l, kvb_h + (long)NOPE * KVL,
                                                kvb_l + (long)NOPE * KVL, nullptr, ve_h, ve_l,
                                                VDIM, KVL, KVL, KVL, VDIM,
                                                0L, (long)(NOPE + VDIM) * KVL, (long)SQ * VDIM);
    // 9. qcat = [q_pass, q_rot] per head (split)
    qcat_split<<<(int)(((long)NH * SQ * KC + 255) / 256), 256>>>(q_pass, q_rot, qcat_h, qcat_l);
    // 10. indexer scores (fp32, exact) + top-k mask
    idx_score2<<<dim3(64, 64), 64>>>(iq, ik, w, score);
    topk_kernel<<<SQ, 256>>>(score, mask);
    // 11. logits[h] = qcat[h] @ kcat[h]^T   (tensor, K=192, causal-N skip)
    hgemm<1, 1, 0, 0><<<dim3(32, 16, 16), 256>>>(qcat_h, qcat_l, kcat_h, kcat_l, P, nullptr, nullptr,
                                                 SQ, KC, KC, KC, SQ,
                                                 (long)SQ * KC, (long)SQ * KC, (long)SQ * SQ);
    // 12. masked softmax -> P hi/lo bf16
    softmax_split<<<dim3(SQ, NH), 256>>>(P, mask, Ph, Pl);
    // 13. out[s, h, :] = P[h] @ v_eff[h]   (tensor, causal-K, direct to output)
    hgemm<0, 0, 1, 0><<<dim3(2, 16, 16), 256>>>(Ph, Pl, ve_h, ve_l, out, nullptr, nullptr,
                                                VDIM, SQ, SQ, VDIM, NH * VDIM,
                                                (long)SQ * SQ, (long)SQ * VDIM, (long)VDIM);
}